// round 1
// baseline (speedup 1.0000x reference)
#include <cuda_runtime.h>
#include <math.h>

#define BB 8
#define NN 8192
#define EE 65536
#define FIN 64
#define HH 128
#define OUTD 256
#define MM (BB*NN)

// ---------------- scratch (static device globals; no allocation) ----------------
__device__ float g_x0[MM*HH];     // 32 MB
__device__ float g_x1[MM*HH];     // 32 MB
__device__ float g_sums[MM*HH];   // 32 MB
__device__ float g_cnt[MM];
__device__ float g_pool[BB*2*HH];

// ---------------- zero helper ----------------
__global__ void zero4_kernel(float4* __restrict__ p, int n4) {
    int i = blockIdx.x * blockDim.x + threadIdx.x;
    if (i < n4) p[i] = make_float4(0.f, 0.f, 0.f, 0.f);
}

// ---------------- edge counts (once; mask layer-invariant) ----------------
__global__ void count_kernel(const int* __restrict__ ei, const float* __restrict__ emask) {
    int e = blockIdx.x * blockDim.x + threadIdx.x;
    if (e >= BB * EE) return;
    int b = e / EE, ee = e - b * EE;
    int tgt = ei[b * 2 * EE + EE + ee];
    float m = emask[b * EE + ee];
    atomicAdd(&g_cnt[b * NN + tgt], m);
}

// ---------------- neighbor aggregation: scatter-add into g_sums ----------------
// 128 threads = one channel each; 8 edges per block.
__global__ void agg_kernel(const float* __restrict__ x, const int* __restrict__ ei,
                           const float* __restrict__ emask) {
    int tid = threadIdx.x;
    int e0 = blockIdx.x * 8;
#pragma unroll
    for (int i = 0; i < 8; i++) {
        int e = e0 + i;
        int b = e / EE, ee = e - b * EE;
        float m = emask[b * EE + ee];
        if (m != 0.f) {
            int src = ei[b * 2 * EE + ee];
            int tgt = ei[b * 2 * EE + EE + ee];
            float v = x[((size_t)(b * NN + src)) * HH + tid] * m;
            atomicAdd(&g_sums[((size_t)(b * NN + tgt)) * HH + tid], v);
        }
    }
}

// ---------------- input GEMM: x0 = relu(feats @ inW + inb) ----------------
// tile 64x128, BK=32, 256 threads (16x16), per-thread 4x8 microtile
__global__ void input_gemm_kernel(const float* __restrict__ A, const float* __restrict__ Bw,
                                  const float* __restrict__ bias, float* __restrict__ xout) {
    __shared__ float As[32][65];
    __shared__ float Bs[32][128];
    const int tx = threadIdx.x, ty = threadIdx.y;
    const int tid = ty * 16 + tx;
    const int m0 = blockIdx.x * 64;
    float acc[4][8];
#pragma unroll
    for (int i = 0; i < 4; i++)
#pragma unroll
        for (int j = 0; j < 8; j++) acc[i][j] = 0.f;

    for (int k0 = 0; k0 < FIN; k0 += 32) {
        const int k = tid & 31, r0 = tid >> 5;
#pragma unroll
        for (int p = 0; p < 8; p++) {
            int row = r0 + p * 8;
            As[k][row] = A[(size_t)(m0 + row) * FIN + k0 + k];
        }
#pragma unroll
        for (int p = 0; p < 4; p++) {
            int row = r0 + p * 8;
            *(float4*)&Bs[row][k * 4] = *(const float4*)&Bw[(size_t)(k0 + row) * HH + k * 4];
        }
        __syncthreads();
#pragma unroll
        for (int kk = 0; kk < 32; kk++) {
            float a[4];
#pragma unroll
            for (int i = 0; i < 4; i++) a[i] = As[kk][ty * 4 + i];
            float4 b0 = *(const float4*)&Bs[kk][tx * 8];
            float4 b1 = *(const float4*)&Bs[kk][tx * 8 + 4];
            float bv[8] = {b0.x, b0.y, b0.z, b0.w, b1.x, b1.y, b1.z, b1.w};
#pragma unroll
            for (int i = 0; i < 4; i++)
#pragma unroll
                for (int j = 0; j < 8; j++) acc[i][j] = fmaf(a[i], bv[j], acc[i][j]);
        }
        __syncthreads();
    }

    const int col = tx * 8;
    float bb[8];
#pragma unroll
    for (int j = 0; j < 8; j++) bb[j] = bias[col + j];
#pragma unroll
    for (int i = 0; i < 4; i++) {
        int grow = m0 + ty * 4 + i;
        float o[8];
#pragma unroll
        for (int j = 0; j < 8; j++) o[j] = fmaxf(acc[i][j] + bb[j], 0.f);
        *(float4*)&xout[(size_t)grow * HH + col]     = make_float4(o[0], o[1], o[2], o[3]);
        *(float4*)&xout[(size_t)grow * HH + col + 4] = make_float4(o[4], o[5], o[6], o[7]);
    }
}

// ---------------- fused layer: h = LN(relu(x@Ws + (sums/cnt)@Wn + bs + bn)) * mask ----------------
__global__ void layer_gemm_kernel(const float* __restrict__ x, const float* __restrict__ sums,
                                  const float* __restrict__ cnt,
                                  const float* __restrict__ Ws, const float* __restrict__ bs,
                                  const float* __restrict__ Wn, const float* __restrict__ bn,
                                  const float* __restrict__ lng, const float* __restrict__ lnb,
                                  const float* __restrict__ nmask, float* __restrict__ xout) {
    __shared__ float As[32][65];
    __shared__ float Bs[32][128];
    const int tx = threadIdx.x, ty = threadIdx.y;
    const int tid = ty * 16 + tx;
    const int m0 = blockIdx.x * 64;
    float acc[4][8];
#pragma unroll
    for (int i = 0; i < 4; i++)
#pragma unroll
        for (int j = 0; j < 8; j++) acc[i][j] = 0.f;

    for (int pass = 0; pass < 2; ++pass) {
        const float* A = pass ? sums : x;
        const float* W = pass ? Wn : Ws;
        for (int k0 = 0; k0 < HH; k0 += 32) {
            const int k = tid & 31, r0 = tid >> 5;
#pragma unroll
            for (int p = 0; p < 8; p++) {
                int row = r0 + p * 8;
                float v = A[(size_t)(m0 + row) * HH + k0 + k];
                if (pass) v *= 1.0f / fmaxf(cnt[m0 + row], 1.0f);
                As[k][row] = v;
            }
#pragma unroll
            for (int p = 0; p < 4; p++) {
                int row = r0 + p * 8;
                *(float4*)&Bs[row][k * 4] = *(const float4*)&W[(size_t)(k0 + row) * HH + k * 4];
            }
            __syncthreads();
#pragma unroll
            for (int kk = 0; kk < 32; kk++) {
                float a[4];
#pragma unroll
                for (int i = 0; i < 4; i++) a[i] = As[kk][ty * 4 + i];
                float4 b0 = *(const float4*)&Bs[kk][tx * 8];
                float4 b1 = *(const float4*)&Bs[kk][tx * 8 + 4];
                float bv[8] = {b0.x, b0.y, b0.z, b0.w, b1.x, b1.y, b1.z, b1.w};
#pragma unroll
                for (int i = 0; i < 4; i++)
#pragma unroll
                    for (int j = 0; j < 8; j++) acc[i][j] = fmaf(a[i], bv[j], acc[i][j]);
            }
            __syncthreads();
        }
    }

    // epilogue: bias + relu + layernorm + mask
    const int col = tx * 8;
    float bb[8], gv[8], bv[8];
#pragma unroll
    for (int j = 0; j < 8; j++) {
        bb[j] = bs[col + j] + bn[col + j];
        gv[j] = lng[col + j];
        bv[j] = lnb[col + j];
    }
#pragma unroll
    for (int i = 0; i < 4; i++) {
        float r[8];
        float s1 = 0.f, s2 = 0.f;
#pragma unroll
        for (int j = 0; j < 8; j++) {
            r[j] = fmaxf(acc[i][j] + bb[j], 0.f);
            s1 += r[j];
            s2 += r[j] * r[j];
        }
        // reduce across the 16 lanes (tx) that hold this row
#pragma unroll
        for (int o = 1; o < 16; o <<= 1) {
            s1 += __shfl_xor_sync(0xffffffffu, s1, o);
            s2 += __shfl_xor_sync(0xffffffffu, s2, o);
        }
        float mean = s1 * (1.0f / 128.0f);
        float var = fmaxf(s2 * (1.0f / 128.0f) - mean * mean, 0.f);
        float inv = rsqrtf(var + 1e-5f);
        int grow = m0 + ty * 4 + i;
        float mk = nmask[grow];
        float o[8];
#pragma unroll
        for (int j = 0; j < 8; j++) o[j] = ((r[j] - mean) * inv * gv[j] + bv[j]) * mk;
        *(float4*)&xout[(size_t)grow * HH + col]     = make_float4(o[0], o[1], o[2], o[3]);
        *(float4*)&xout[(size_t)grow * HH + col + 4] = make_float4(o[4], o[5], o[6], o[7]);
    }
}

// ---------------- global mean/max pool ----------------
// grid = B*4 blocks; block handles 32 channels of one batch; 8 warps stride nodes
__global__ void pool_kernel(const float* __restrict__ x, const float* __restrict__ nmask,
                            float* __restrict__ pool) {
    int b = blockIdx.x >> 2;
    int c0 = (blockIdx.x & 3) * 32;
    int w = threadIdx.x >> 5, lane = threadIdx.x & 31;
    int c = c0 + lane;
    float s = 0.f, mx = -INFINITY, cv = 0.f;
    for (int n = w; n < NN; n += 8) {
        float mk = nmask[b * NN + n];
        float v = x[((size_t)(b * NN + n)) * HH + c];
        s += v * mk;
        if (mk > 0.f) mx = fmaxf(mx, v * mk);
        cv += mk;
    }
    __shared__ float ss[8][32], sm[8][32], sc[8];
    ss[w][lane] = s;
    sm[w][lane] = mx;
    if (lane == 0) sc[w] = cv;
    __syncthreads();
    if (threadIdx.x < 32) {
        float ts = 0.f, tm = -INFINITY, tc = 0.f;
#pragma unroll
        for (int i = 0; i < 8; i++) {
            ts += ss[i][threadIdx.x];
            tm = fmaxf(tm, sm[i][threadIdx.x]);
            tc += sc[i];
        }
        pool[b * 256 + c0 + threadIdx.x] = ts / fmaxf(tc, 1.0f);
        pool[b * 256 + 128 + c0 + threadIdx.x] = tm;
    }
}

// ---------------- output MLP: out = relu(g@W1+b1)@W2 + b2 ----------------
__global__ void mlp_kernel(const float* __restrict__ pool, const float* __restrict__ W1,
                           const float* __restrict__ b1, const float* __restrict__ W2,
                           const float* __restrict__ b2, float* __restrict__ out) {
    __shared__ float gs[256], hs[128];
    int b = blockIdx.x, tid = threadIdx.x;
    gs[tid] = pool[b * 256 + tid];
    __syncthreads();
    if (tid < 128) {
        float a = b1[tid];
        for (int k = 0; k < 256; k++) a = fmaf(gs[k], W1[k * 128 + tid], a);
        hs[tid] = fmaxf(a, 0.f);
    }
    __syncthreads();
    float a = b2[tid];
    for (int k = 0; k < 128; k++) a = fmaf(hs[k], W2[k * 256 + tid], a);
    out[b * 256 + tid] = a;
}

// ---------------- launch ----------------
extern "C" void kernel_launch(void* const* d_in, const int* in_sizes, int n_in,
                              void* d_out, int out_size) {
    const float* feats = (const float*)d_in[0];
    const int*   ei    = (const int*)d_in[1];
    const float* nmask = (const float*)d_in[2];
    const float* emask = (const float*)d_in[3];
    const float* inW   = (const float*)d_in[4];
    const float* inb   = (const float*)d_in[5];
    const float* sW    = (const float*)d_in[6];
    const float* sb    = (const float*)d_in[7];
    const float* nW    = (const float*)d_in[8];
    const float* nb    = (const float*)d_in[9];
    const float* lng   = (const float*)d_in[10];
    const float* lnb   = (const float*)d_in[11];
    const float* w1    = (const float*)d_in[12];
    const float* b1    = (const float*)d_in[13];
    const float* w2    = (const float*)d_in[14];
    const float* b2    = (const float*)d_in[15];

    float *x0, *x1, *sums, *cnt, *pool;
    cudaGetSymbolAddress((void**)&x0,   g_x0);
    cudaGetSymbolAddress((void**)&x1,   g_x1);
    cudaGetSymbolAddress((void**)&sums, g_sums);
    cudaGetSymbolAddress((void**)&cnt,  g_cnt);
    cudaGetSymbolAddress((void**)&pool, g_pool);

    dim3 blk2(16, 16);

    // counts (layer-invariant)
    zero4_kernel<<<(MM / 4 + 255) / 256, 256>>>((float4*)cnt, MM / 4);
    count_kernel<<<(BB * EE + 255) / 256, 256>>>(ei, emask);

    // input projection
    input_gemm_kernel<<<MM / 64, blk2>>>(feats, inW, inb, x0);

    float* xin = x0;
    float* xo  = x1;
    for (int l = 0; l < 3; l++) {
        zero4_kernel<<<(MM * HH / 4 + 255) / 256, 256>>>((float4*)sums, MM * HH / 4);
        agg_kernel<<<BB * EE / 8, 128>>>(xin, ei, emask);
        layer_gemm_kernel<<<MM / 64, blk2>>>(xin, sums, cnt,
                                             sW + (size_t)l * HH * HH, sb + l * HH,
                                             nW + (size_t)l * HH * HH, nb + l * HH,
                                             lng + l * HH, lnb + l * HH,
                                             nmask, xo);
        float* t = xin; xin = xo; xo = t;
    }

    pool_kernel<<<BB * 4, 256>>>(xin, nmask, pool);
    mlp_kernel<<<BB, 256>>>(pool, w1, b1, w2, b2, (float*)d_out);
}

// round 2
// speedup vs baseline: 1.0803x; 1.0803x over previous
#include <cuda_runtime.h>
#include <math.h>

#define BB 8
#define NN 8192
#define EE 65536
#define FIN 64
#define HH 128
#define OUTD 256
#define MM (BB*NN)
#define ETOT (BB*EE)

// ---------------- scratch (static device globals; no allocation) ----------------
__device__ float g_x0[MM*HH];     // 32 MB
__device__ float g_x1[MM*HH];     // 32 MB
__device__ float g_agg[MM*HH];    // 32 MB (aggregated neighbor means)
__device__ float g_cntf[MM];
__device__ int   g_cnti[MM];
__device__ int   g_off[MM + 4];
__device__ int   g_cur[MM];
__device__ int   g_csrc[ETOT];
__device__ float g_cw[ETOT];
__device__ float g_pool[BB*2*HH];

// ---------------- f32x2 packed helpers ----------------
typedef unsigned long long ull;
__device__ __forceinline__ ull pk2(float a, float b) {
    ull r; asm("mov.b64 %0, {%1,%2};" : "=l"(r) : "f"(a), "f"(b)); return r;
}
__device__ __forceinline__ void fma2(ull &d, ull a, ull b) {
    asm("fma.rn.f32x2 %0, %1, %2, %0;" : "+l"(d) : "l"(a), "l"(b));
}
__device__ __forceinline__ float2 up2(ull v) {
    float2 f; asm("mov.b64 {%0,%1}, %2;" : "=f"(f.x), "=f"(f.y) : "l"(v)); return f;
}

// ---------------- zero helper ----------------
__global__ void zero4_kernel(float4* __restrict__ p, int n4) {
    int i = blockIdx.x * blockDim.x + threadIdx.x;
    if (i < n4) p[i] = make_float4(0.f, 0.f, 0.f, 0.f);
}

// ---------------- edge counts (float mask sum + int CSR count) ----------------
__global__ void count_kernel(const int* __restrict__ ei, const float* __restrict__ emask,
                             float* __restrict__ cntf, int* __restrict__ cnti) {
    int e = blockIdx.x * blockDim.x + threadIdx.x;
    if (e >= ETOT) return;
    int b = e / EE, ee = e - b * EE;
    int tgt = ei[b * 2 * EE + EE + ee] + b * NN;
    float m = emask[e];
    atomicAdd(&cntf[tgt], m);
    if (m != 0.f) atomicAdd(&cnti[tgt], 1);
}

// ---------------- exclusive scan over 64K counts (single block) ----------------
__global__ void scan_kernel(const int* __restrict__ cnt, int* __restrict__ off,
                            int* __restrict__ cur) {
    __shared__ int sh[1024];
    int t = threadIdx.x;
    int base = t * (MM / 1024);
    int s = 0;
#pragma unroll 8
    for (int i = 0; i < MM / 1024; i++) s += cnt[base + i];
    sh[t] = s;
    __syncthreads();
    // Hillis-Steele inclusive scan
    for (int d = 1; d < 1024; d <<= 1) {
        int v = (t >= d) ? sh[t - d] : 0;
        __syncthreads();
        sh[t] += v;
        __syncthreads();
    }
    int run = sh[t] - s;  // exclusive prefix for this thread's chunk
    for (int i = 0; i < MM / 1024; i++) {
        int idx = base + i;
        off[idx] = run;
        cur[idx] = run;
        run += cnt[idx];
    }
    if (t == 1023) off[MM] = run;
}

// ---------------- CSR fill ----------------
__global__ void fill_kernel(const int* __restrict__ ei, const float* __restrict__ emask,
                            int* __restrict__ cur, int* __restrict__ csrc,
                            float* __restrict__ cw) {
    int e = blockIdx.x * blockDim.x + threadIdx.x;
    if (e >= ETOT) return;
    int b = e / EE, ee = e - b * EE;
    float m = emask[e];
    if (m == 0.f) return;
    int src = ei[b * 2 * EE + ee] + b * NN;
    int tgt = ei[b * 2 * EE + EE + ee] + b * NN;
    int slot = atomicAdd(&cur[tgt], 1);
    csrc[slot] = src;
    cw[slot] = m;
}

// ---------------- CSR aggregation: warp per node, gather + mean ----------------
__global__ void agg_csr_kernel(const float* __restrict__ x, const int* __restrict__ off,
                               const int* __restrict__ csrc, const float* __restrict__ cw,
                               const float* __restrict__ cntf, float* __restrict__ outm) {
    int warp = (blockIdx.x * blockDim.x + threadIdx.x) >> 5;
    int lane = threadIdx.x & 31;
    if (warp >= MM) return;
    int beg = off[warp], end = off[warp + 1];
    float ax = 0.f, ay = 0.f, az = 0.f, aw = 0.f;
    int e = beg;
    for (; e + 2 <= end; e += 2) {
        int s0 = csrc[e], s1 = csrc[e + 1];
        float w0 = cw[e], w1 = cw[e + 1];
        float4 v0 = *(const float4*)&x[(size_t)s0 * HH + lane * 4];
        float4 v1 = *(const float4*)&x[(size_t)s1 * HH + lane * 4];
        ax += v0.x * w0 + v1.x * w1;
        ay += v0.y * w0 + v1.y * w1;
        az += v0.z * w0 + v1.z * w1;
        aw += v0.w * w0 + v1.w * w1;
    }
    if (e < end) {
        int s0 = csrc[e];
        float w0 = cw[e];
        float4 v0 = *(const float4*)&x[(size_t)s0 * HH + lane * 4];
        ax += v0.x * w0; ay += v0.y * w0; az += v0.z * w0; aw += v0.w * w0;
    }
    float inv = 1.0f / fmaxf(cntf[warp], 1.0f);
    *(float4*)&outm[(size_t)warp * HH + lane * 4] =
        make_float4(ax * inv, ay * inv, az * inv, aw * inv);
}

// ---------------- input GEMM: x0 = relu(feats @ inW + inb), FFMA2 ----------------
__global__ void input_gemm_kernel(const float* __restrict__ A, const float* __restrict__ Bw,
                                  const float* __restrict__ bias, float* __restrict__ xout) {
    __shared__ float As[32][65];
    __shared__ float Bs[32][128];
    const int tx = threadIdx.x, ty = threadIdx.y;
    const int tid = ty * 16 + tx;
    const int m0 = blockIdx.x * 64;
    ull acc[4][4];
#pragma unroll
    for (int i = 0; i < 4; i++)
#pragma unroll
        for (int j = 0; j < 4; j++) acc[i][j] = 0ull;

    for (int k0 = 0; k0 < FIN; k0 += 32) {
        const int k = tid & 31, r0 = tid >> 5;
#pragma unroll
        for (int p = 0; p < 8; p++) {
            int row = r0 + p * 8;
            As[k][row] = A[(size_t)(m0 + row) * FIN + k0 + k];
        }
#pragma unroll
        for (int p = 0; p < 4; p++) {
            int row = r0 + p * 8;
            *(float4*)&Bs[row][k * 4] = *(const float4*)&Bw[(size_t)(k0 + row) * HH + k * 4];
        }
        __syncthreads();
#pragma unroll
        for (int kk = 0; kk < 32; kk++) {
            ull a2[4];
#pragma unroll
            for (int i = 0; i < 4; i++) {
                float a = As[kk][ty * 4 + i];
                a2[i] = pk2(a, a);
            }
            float4 b0 = *(const float4*)&Bs[kk][tx * 8];
            float4 b1 = *(const float4*)&Bs[kk][tx * 8 + 4];
            ull bp[4] = {pk2(b0.x, b0.y), pk2(b0.z, b0.w), pk2(b1.x, b1.y), pk2(b1.z, b1.w)};
#pragma unroll
            for (int i = 0; i < 4; i++)
#pragma unroll
                for (int j = 0; j < 4; j++) fma2(acc[i][j], a2[i], bp[j]);
        }
        __syncthreads();
    }

    const int col = tx * 8;
    float bb[8];
#pragma unroll
    for (int j = 0; j < 8; j++) bb[j] = bias[col + j];
#pragma unroll
    for (int i = 0; i < 4; i++) {
        int grow = m0 + ty * 4 + i;
        float o[8];
#pragma unroll
        for (int j = 0; j < 4; j++) {
            float2 p = up2(acc[i][j]);
            o[2 * j] = fmaxf(p.x + bb[2 * j], 0.f);
            o[2 * j + 1] = fmaxf(p.y + bb[2 * j + 1], 0.f);
        }
        *(float4*)&xout[(size_t)grow * HH + col]     = make_float4(o[0], o[1], o[2], o[3]);
        *(float4*)&xout[(size_t)grow * HH + col + 4] = make_float4(o[4], o[5], o[6], o[7]);
    }
}

// ---------------- fused layer: h = LN(relu(x@Ws + agg@Wn + bs + bn)) * mask, FFMA2 ----------------
__global__ void layer_gemm_kernel(const float* __restrict__ x, const float* __restrict__ agg,
                                  const float* __restrict__ Ws, const float* __restrict__ bs,
                                  const float* __restrict__ Wn, const float* __restrict__ bn,
                                  const float* __restrict__ lng, const float* __restrict__ lnb,
                                  const float* __restrict__ nmask, float* __restrict__ xout) {
    __shared__ float As[32][65];
    __shared__ float Bs[32][128];
    const int tx = threadIdx.x, ty = threadIdx.y;
    const int tid = ty * 16 + tx;
    const int m0 = blockIdx.x * 64;
    ull acc[4][4];
#pragma unroll
    for (int i = 0; i < 4; i++)
#pragma unroll
        for (int j = 0; j < 4; j++) acc[i][j] = 0ull;

    for (int pass = 0; pass < 2; ++pass) {
        const float* A = pass ? agg : x;
        const float* W = pass ? Wn : Ws;
        for (int k0 = 0; k0 < HH; k0 += 32) {
            const int k = tid & 31, r0 = tid >> 5;
#pragma unroll
            for (int p = 0; p < 8; p++) {
                int row = r0 + p * 8;
                As[k][row] = A[(size_t)(m0 + row) * HH + k0 + k];
            }
#pragma unroll
            for (int p = 0; p < 4; p++) {
                int row = r0 + p * 8;
                *(float4*)&Bs[row][k * 4] = *(const float4*)&W[(size_t)(k0 + row) * HH + k * 4];
            }
            __syncthreads();
#pragma unroll
            for (int kk = 0; kk < 32; kk++) {
                ull a2[4];
#pragma unroll
                for (int i = 0; i < 4; i++) {
                    float a = As[kk][ty * 4 + i];
                    a2[i] = pk2(a, a);
                }
                float4 b0 = *(const float4*)&Bs[kk][tx * 8];
                float4 b1 = *(const float4*)&Bs[kk][tx * 8 + 4];
                ull bp[4] = {pk2(b0.x, b0.y), pk2(b0.z, b0.w), pk2(b1.x, b1.y), pk2(b1.z, b1.w)};
#pragma unroll
                for (int i = 0; i < 4; i++)
#pragma unroll
                    for (int j = 0; j < 4; j++) fma2(acc[i][j], a2[i], bp[j]);
            }
            __syncthreads();
        }
    }

    // epilogue: bias + relu + layernorm + mask
    const int col = tx * 8;
    float bb[8], gv[8], bv[8];
#pragma unroll
    for (int j = 0; j < 8; j++) {
        bb[j] = bs[col + j] + bn[col + j];
        gv[j] = lng[col + j];
        bv[j] = lnb[col + j];
    }
#pragma unroll
    for (int i = 0; i < 4; i++) {
        float r[8];
#pragma unroll
        for (int j = 0; j < 4; j++) {
            float2 p = up2(acc[i][j]);
            r[2 * j] = fmaxf(p.x + bb[2 * j], 0.f);
            r[2 * j + 1] = fmaxf(p.y + bb[2 * j + 1], 0.f);
        }
        float s1 = 0.f, s2 = 0.f;
#pragma unroll
        for (int j = 0; j < 8; j++) {
            s1 += r[j];
            s2 += r[j] * r[j];
        }
#pragma unroll
        for (int o = 1; o < 16; o <<= 1) {
            s1 += __shfl_xor_sync(0xffffffffu, s1, o);
            s2 += __shfl_xor_sync(0xffffffffu, s2, o);
        }
        float mean = s1 * (1.0f / 128.0f);
        float var = fmaxf(s2 * (1.0f / 128.0f) - mean * mean, 0.f);
        float inv = rsqrtf(var + 1e-5f);
        int grow = m0 + ty * 4 + i;
        float mk = nmask[grow];
        float o[8];
#pragma unroll
        for (int j = 0; j < 8; j++) o[j] = ((r[j] - mean) * inv * gv[j] + bv[j]) * mk;
        *(float4*)&xout[(size_t)grow * HH + col]     = make_float4(o[0], o[1], o[2], o[3]);
        *(float4*)&xout[(size_t)grow * HH + col + 4] = make_float4(o[4], o[5], o[6], o[7]);
    }
}

// ---------------- global mean/max pool ----------------
__global__ void pool_kernel(const float* __restrict__ x, const float* __restrict__ nmask,
                            float* __restrict__ pool) {
    int b = blockIdx.x >> 2;
    int c0 = (blockIdx.x & 3) * 32;
    int w = threadIdx.x >> 5, lane = threadIdx.x & 31;
    int c = c0 + lane;
    float s = 0.f, mx = -INFINITY, cv = 0.f;
    for (int n = w; n < NN; n += 8) {
        float mk = nmask[b * NN + n];
        float v = x[((size_t)(b * NN + n)) * HH + c];
        s += v * mk;
        if (mk > 0.f) mx = fmaxf(mx, v * mk);
        cv += mk;
    }
    __shared__ float ss[8][32], sm[8][32], sc[8];
    ss[w][lane] = s;
    sm[w][lane] = mx;
    if (lane == 0) sc[w] = cv;
    __syncthreads();
    if (threadIdx.x < 32) {
        float ts = 0.f, tm = -INFINITY, tc = 0.f;
#pragma unroll
        for (int i = 0; i < 8; i++) {
            ts += ss[i][threadIdx.x];
            tm = fmaxf(tm, sm[i][threadIdx.x]);
            tc += sc[i];
        }
        pool[b * 256 + c0 + threadIdx.x] = ts / fmaxf(tc, 1.0f);
        pool[b * 256 + 128 + c0 + threadIdx.x] = tm;
    }
}

// ---------------- output MLP ----------------
__global__ void mlp_kernel(const float* __restrict__ pool, const float* __restrict__ W1,
                           const float* __restrict__ b1, const float* __restrict__ W2,
                           const float* __restrict__ b2, float* __restrict__ out) {
    __shared__ float gs[256], hs[128];
    int b = blockIdx.x, tid = threadIdx.x;
    gs[tid] = pool[b * 256 + tid];
    __syncthreads();
    if (tid < 128) {
        float a = b1[tid];
        for (int k = 0; k < 256; k++) a = fmaf(gs[k], W1[k * 128 + tid], a);
        hs[tid] = fmaxf(a, 0.f);
    }
    __syncthreads();
    float a = b2[tid];
    for (int k = 0; k < 128; k++) a = fmaf(hs[k], W2[k * 256 + tid], a);
    out[b * 256 + tid] = a;
}

// ---------------- launch ----------------
extern "C" void kernel_launch(void* const* d_in, const int* in_sizes, int n_in,
                              void* d_out, int out_size) {
    const float* feats = (const float*)d_in[0];
    const int*   ei    = (const int*)d_in[1];
    const float* nmask = (const float*)d_in[2];
    const float* emask = (const float*)d_in[3];
    const float* inW   = (const float*)d_in[4];
    const float* inb   = (const float*)d_in[5];
    const float* sW    = (const float*)d_in[6];
    const float* sb    = (const float*)d_in[7];
    const float* nW    = (const float*)d_in[8];
    const float* nb    = (const float*)d_in[9];
    const float* lng   = (const float*)d_in[10];
    const float* lnb   = (const float*)d_in[11];
    const float* w1    = (const float*)d_in[12];
    const float* b1    = (const float*)d_in[13];
    const float* w2    = (const float*)d_in[14];
    const float* b2    = (const float*)d_in[15];

    float *x0, *x1, *agg, *cntf, *pool, *cw;
    int *cnti, *off, *cur, *csrc;
    cudaGetSymbolAddress((void**)&x0,   g_x0);
    cudaGetSymbolAddress((void**)&x1,   g_x1);
    cudaGetSymbolAddress((void**)&agg,  g_agg);
    cudaGetSymbolAddress((void**)&cntf, g_cntf);
    cudaGetSymbolAddress((void**)&cnti, g_cnti);
    cudaGetSymbolAddress((void**)&off,  g_off);
    cudaGetSymbolAddress((void**)&cur,  g_cur);
    cudaGetSymbolAddress((void**)&csrc, g_csrc);
    cudaGetSymbolAddress((void**)&cw,   g_cw);
    cudaGetSymbolAddress((void**)&pool, g_pool);

    dim3 blk2(16, 16);

    // CSR build (once per launch; mask/topology are layer-invariant)
    zero4_kernel<<<(MM / 4 + 255) / 256, 256>>>((float4*)cntf, MM / 4);
    zero4_kernel<<<(MM / 4 + 255) / 256, 256>>>((float4*)cnti, MM / 4);
    count_kernel<<<(ETOT + 255) / 256, 256>>>(ei, emask, cntf, cnti);
    scan_kernel<<<1, 1024>>>(cnti, off, cur);
    fill_kernel<<<(ETOT + 255) / 256, 256>>>(ei, emask, cur, csrc, cw);

    // input projection
    input_gemm_kernel<<<MM / 64, blk2>>>(feats, inW, inb, x0);

    float* xin = x0;
    float* xo  = x1;
    for (int l = 0; l < 3; l++) {
        agg_csr_kernel<<<MM * 32 / 256, 256>>>(xin, off, csrc, cw, cntf, agg);
        layer_gemm_kernel<<<MM / 64, blk2>>>(xin, agg,
                                             sW + (size_t)l * HH * HH, sb + l * HH,
                                             nW + (size_t)l * HH * HH, nb + l * HH,
                                             lng + l * HH, lnb + l * HH,
                                             nmask, xo);
        float* t = xin; xin = xo; xo = t;
    }

    pool_kernel<<<BB * 4, 256>>>(xin, nmask, pool);
    mlp_kernel<<<BB, 256>>>(pool, w1, b1, w2, b2, (float*)d_out);
}

// round 3
// speedup vs baseline: 2.4415x; 2.2600x over previous
#include <cuda_runtime.h>
#include <math.h>

#define BB 8
#define NN 8192
#define EE 65536
#define FIN 64
#define HH 128
#define OUTD 256
#define MM (BB*NN)
#define ETOT (BB*EE)

// ---------------- scratch (static device globals; no allocation) ----------------
__device__ float g_x0[MM*HH];     // 32 MB
__device__ float g_x1[MM*HH];     // 32 MB
__device__ float g_agg[MM*HH];    // 32 MB
__device__ int   g_cnti[MM];
__device__ int   g_off[MM + 4];
__device__ int   g_cur[MM];
__device__ int   g_bsum[64];
__device__ int   g_boff[64];
__device__ int   g_csrc[ETOT];
__device__ float g_cw[ETOT];
__device__ float g_pp[256*128];
__device__ float g_pm[256*128];
__device__ float g_pool[BB*2*HH];

// ---------------- f32x2 packed helpers ----------------
typedef unsigned long long ull;
__device__ __forceinline__ ull pk2(float a, float b) {
    ull r; asm("mov.b64 %0, {%1,%2};" : "=l"(r) : "f"(a), "f"(b)); return r;
}
__device__ __forceinline__ void fma2(ull &d, ull a, ull b) {
    asm("fma.rn.f32x2 %0, %1, %2, %0;" : "+l"(d) : "l"(a), "l"(b));
}
__device__ __forceinline__ float2 up2(ull v) {
    float2 f; asm("mov.b64 {%0,%1}, %2;" : "=f"(f.x), "=f"(f.y) : "l"(v)); return f;
}

// ---------------- zero helper ----------------
__global__ void zero4_kernel(float4* __restrict__ p, int n4) {
    int i = blockIdx.x * blockDim.x + threadIdx.x;
    if (i < n4) p[i] = make_float4(0.f, 0.f, 0.f, 0.f);
}

// ---------------- CSR build ----------------
__global__ void count_kernel(const int* __restrict__ ei, const float* __restrict__ emask,
                             int* __restrict__ cnti) {
    int e = blockIdx.x * blockDim.x + threadIdx.x;
    if (e >= ETOT) return;
    int b = e / EE, ee = e - b * EE;
    if (emask[e] != 0.f) {
        int tgt = ei[b * 2 * EE + EE + ee] + b * NN;
        atomicAdd(&cnti[tgt], 1);
    }
}

__global__ void psum_kernel(const int* __restrict__ cnt, int* __restrict__ bsum) {
    __shared__ int sh[1024];
    int t = threadIdx.x;
    sh[t] = cnt[blockIdx.x * 1024 + t];
    __syncthreads();
    for (int d = 512; d; d >>= 1) {
        if (t < d) sh[t] += sh[t + d];
        __syncthreads();
    }
    if (t == 0) bsum[blockIdx.x] = sh[0];
}

__global__ void scanb_kernel(const int* __restrict__ bsum, int* __restrict__ boff,
                             int* __restrict__ off) {
    __shared__ int sh[64];
    int t = threadIdx.x;
    int v = bsum[t];
    sh[t] = v;
    __syncthreads();
    for (int d = 1; d < 64; d <<= 1) {
        int u = (t >= d) ? sh[t - d] : 0;
        __syncthreads();
        sh[t] += u;
        __syncthreads();
    }
    boff[t] = sh[t] - v;
    if (t == 63) off[MM] = sh[63];
}

__global__ void emit_kernel(const int* __restrict__ cnt, const int* __restrict__ boff,
                            int* __restrict__ off, int* __restrict__ cur) {
    __shared__ int sh[1024];
    int t = threadIdx.x, g = blockIdx.x * 1024 + t;
    int v = cnt[g];
    sh[t] = v;
    __syncthreads();
    for (int d = 1; d < 1024; d <<= 1) {
        int u = (t >= d) ? sh[t - d] : 0;
        __syncthreads();
        sh[t] += u;
        __syncthreads();
    }
    int ex = sh[t] - v + boff[blockIdx.x];
    off[g] = ex;
    cur[g] = ex;
}

__global__ void fill_kernel(const int* __restrict__ ei, const float* __restrict__ emask,
                            int* __restrict__ cur, int* __restrict__ csrc,
                            float* __restrict__ cw) {
    int e = blockIdx.x * blockDim.x + threadIdx.x;
    if (e >= ETOT) return;
    int b = e / EE, ee = e - b * EE;
    float m = emask[e];
    if (m == 0.f) return;
    int src = ei[b * 2 * EE + ee] + b * NN;
    int tgt = ei[b * 2 * EE + EE + ee] + b * NN;
    int slot = atomicAdd(&cur[tgt], 1);
    csrc[slot] = src;
    cw[slot] = m;
}

// ---------------- CSR aggregation: warp per node ----------------
__global__ void agg_csr_kernel(const float* __restrict__ x, const int* __restrict__ off,
                               const int* __restrict__ csrc, const float* __restrict__ cw,
                               float* __restrict__ outm) {
    int warp = (blockIdx.x * blockDim.x + threadIdx.x) >> 5;
    int lane = threadIdx.x & 31;
    if (warp >= MM) return;
    int beg = off[warp], end = off[warp + 1];
    float ax = 0.f, ay = 0.f, az = 0.f, aw = 0.f, ws = 0.f;
    int e = beg;
    for (; e + 2 <= end; e += 2) {
        int s0 = csrc[e], s1 = csrc[e + 1];
        float w0 = cw[e], w1 = cw[e + 1];
        float4 v0 = *(const float4*)&x[(size_t)s0 * HH + lane * 4];
        float4 v1 = *(const float4*)&x[(size_t)s1 * HH + lane * 4];
        ax += v0.x * w0 + v1.x * w1;
        ay += v0.y * w0 + v1.y * w1;
        az += v0.z * w0 + v1.z * w1;
        aw += v0.w * w0 + v1.w * w1;
        ws += w0 + w1;
    }
    if (e < end) {
        int s0 = csrc[e];
        float w0 = cw[e];
        float4 v0 = *(const float4*)&x[(size_t)s0 * HH + lane * 4];
        ax += v0.x * w0; ay += v0.y * w0; az += v0.z * w0; aw += v0.w * w0;
        ws += w0;
    }
    float inv = 1.0f / fmaxf(ws, 1.0f);
    *(float4*)&outm[(size_t)warp * HH + lane * 4] =
        make_float4(ax * inv, ay * inv, az * inv, aw * inv);
}

// ================= GEMM kernels: 128x128 CTA tile, (8,32) threads, =================
// ================= r4 x c16 microtile, 2x2 f32x2 pair blocking      =================
#define ASTR 130  // padded A-tile row stride (k-major): bank-spread

// ---------------- input GEMM: x0 = relu(feats @ inW + inb) ----------------
__global__ void __launch_bounds__(256, 2)
input_gemm_kernel(const float* __restrict__ A, const float* __restrict__ Bw,
                  const float* __restrict__ bias, float* __restrict__ xout) {
    __shared__ __align__(16) float As[32 * ASTR];
    __shared__ __align__(16) float Bs[32 * 128];
    const int tx = threadIdx.x, ty = threadIdx.y;
    const int tid = ty * 8 + tx;
    const int m0 = blockIdx.x * 128;

    ull accA[2][8], accB[2][8];
#pragma unroll
    for (int rp = 0; rp < 2; rp++)
#pragma unroll
        for (int jp = 0; jp < 8; jp++) { accA[rp][jp] = 0ull; accB[rp][jp] = 0ull; }

    for (int k0 = 0; k0 < FIN; k0 += 32) {
        // stage A tile: 128 rows x 32 k
#pragma unroll
        for (int p = 0; p < 4; p++) {
            int idx = p * 256 + tid;
            int row = idx >> 3, c4 = idx & 7;
            float4 va = *(const float4*)&A[(size_t)(m0 + row) * FIN + k0 + c4 * 4];
            As[(c4 * 4 + 0) * ASTR + row] = va.x;
            As[(c4 * 4 + 1) * ASTR + row] = va.y;
            As[(c4 * 4 + 2) * ASTR + row] = va.z;
            As[(c4 * 4 + 3) * ASTR + row] = va.w;
        }
        // stage B tile: 32 k x 128 n, xor-swizzled in 16B units
#pragma unroll
        for (int p = 0; p < 4; p++) {
            int idx = p * 256 + tid;
            int k = idx >> 5, c4 = idx & 31;
            float4 w4 = *(const float4*)&Bw[(size_t)(k0 + k) * HH + c4 * 4];
            int p4 = c4 ^ (c4 >> 3);
            *(float4*)&Bs[k * 128 + p4 * 4] = w4;
        }
        __syncthreads();
#pragma unroll
        for (int kk = 0; kk < 32; kk++) {
            ull a2[2], a2s[2], b2[8];
            const float* ak = &As[kk * ASTR + ty * 4];
#pragma unroll
            for (int rp = 0; rp < 2; rp++) {
                float2 av = *(const float2*)&ak[2 * rp];
                a2[rp]  = pk2(av.x, av.y);
                a2s[rp] = pk2(av.y, av.x);
            }
            const float* bk = &Bs[kk * 128];
#pragma unroll
            for (int u = 0; u < 4; u++) {
                int c4 = tx * 4 + u;
                int p4 = c4 ^ (c4 >> 3);
                float4 q = *(const float4*)&bk[p4 * 4];
                b2[2 * u]     = pk2(q.x, q.y);
                b2[2 * u + 1] = pk2(q.z, q.w);
            }
#pragma unroll
            for (int rp = 0; rp < 2; rp++)
#pragma unroll
                for (int jp = 0; jp < 8; jp++) {
                    fma2(accA[rp][jp], a2[rp],  b2[jp]);
                    fma2(accB[rp][jp], a2s[rp], b2[jp]);
                }
        }
        __syncthreads();
    }

    // epilogue: bias + relu
    float rr[4][16];
#pragma unroll
    for (int rp = 0; rp < 2; rp++)
#pragma unroll
        for (int jp = 0; jp < 8; jp++) {
            float2 pA = up2(accA[rp][jp]), pB = up2(accB[rp][jp]);
            rr[2 * rp][2 * jp]         = pA.x;
            rr[2 * rp + 1][2 * jp + 1] = pA.y;
            rr[2 * rp + 1][2 * jp]     = pB.x;
            rr[2 * rp][2 * jp + 1]     = pB.y;
        }
    const int col = tx * 16;
    float bb[16];
#pragma unroll
    for (int j = 0; j < 16; j++) bb[j] = bias[col + j];
#pragma unroll
    for (int i = 0; i < 4; i++) {
        int grow = m0 + ty * 4 + i;
        float o[16];
#pragma unroll
        for (int j = 0; j < 16; j++) o[j] = fmaxf(rr[i][j] + bb[j], 0.f);
#pragma unroll
        for (int q = 0; q < 4; q++)
            *(float4*)&xout[(size_t)grow * HH + col + q * 4] =
                make_float4(o[4 * q], o[4 * q + 1], o[4 * q + 2], o[4 * q + 3]);
    }
}

// ---------------- fused layer: h = LN(relu(x@Ws + agg@Wn + bs + bn)) * mask ----------------
__global__ void __launch_bounds__(256, 2)
layer_gemm_kernel(const float* __restrict__ x, const float* __restrict__ agg,
                  const float* __restrict__ Ws, const float* __restrict__ bs,
                  const float* __restrict__ Wn, const float* __restrict__ bn,
                  const float* __restrict__ lng, const float* __restrict__ lnb,
                  const float* __restrict__ nmask, float* __restrict__ xout) {
    __shared__ __align__(16) float As[32 * ASTR];
    __shared__ __align__(16) float Bs[32 * 128];
    const int tx = threadIdx.x, ty = threadIdx.y;
    const int tid = ty * 8 + tx;
    const int m0 = blockIdx.x * 128;

    ull accA[2][8], accB[2][8];
#pragma unroll
    for (int rp = 0; rp < 2; rp++)
#pragma unroll
        for (int jp = 0; jp < 8; jp++) { accA[rp][jp] = 0ull; accB[rp][jp] = 0ull; }

    for (int pass = 0; pass < 2; ++pass) {
        const float* Aq = pass ? agg : x;
        const float* W  = pass ? Wn : Ws;
        for (int k0 = 0; k0 < HH; k0 += 32) {
#pragma unroll
            for (int p = 0; p < 4; p++) {
                int idx = p * 256 + tid;
                int row = idx >> 3, c4 = idx & 7;
                float4 va = *(const float4*)&Aq[(size_t)(m0 + row) * HH + k0 + c4 * 4];
                As[(c4 * 4 + 0) * ASTR + row] = va.x;
                As[(c4 * 4 + 1) * ASTR + row] = va.y;
                As[(c4 * 4 + 2) * ASTR + row] = va.z;
                As[(c4 * 4 + 3) * ASTR + row] = va.w;
            }
#pragma unroll
            for (int p = 0; p < 4; p++) {
                int idx = p * 256 + tid;
                int k = idx >> 5, c4 = idx & 31;
                float4 w4 = *(const float4*)&W[(size_t)(k0 + k) * HH + c4 * 4];
                int p4 = c4 ^ (c4 >> 3);
                *(float4*)&Bs[k * 128 + p4 * 4] = w4;
            }
            __syncthreads();
#pragma unroll
            for (int kk = 0; kk < 32; kk++) {
                ull a2[2], a2s[2], b2[8];
                const float* ak = &As[kk * ASTR + ty * 4];
#pragma unroll
                for (int rp = 0; rp < 2; rp++) {
                    float2 av = *(const float2*)&ak[2 * rp];
                    a2[rp]  = pk2(av.x, av.y);
                    a2s[rp] = pk2(av.y, av.x);
                }
                const float* bk = &Bs[kk * 128];
#pragma unroll
                for (int u = 0; u < 4; u++) {
                    int c4 = tx * 4 + u;
                    int p4 = c4 ^ (c4 >> 3);
                    float4 q = *(const float4*)&bk[p4 * 4];
                    b2[2 * u]     = pk2(q.x, q.y);
                    b2[2 * u + 1] = pk2(q.z, q.w);
                }
#pragma unroll
                for (int rp = 0; rp < 2; rp++)
#pragma unroll
                    for (int jp = 0; jp < 8; jp++) {
                        fma2(accA[rp][jp], a2[rp],  b2[jp]);
                        fma2(accB[rp][jp], a2s[rp], b2[jp]);
                    }
            }
            __syncthreads();
        }
    }

    // epilogue: bias + relu + layernorm + mask
    float rr[4][16];
#pragma unroll
    for (int rp = 0; rp < 2; rp++)
#pragma unroll
        for (int jp = 0; jp < 8; jp++) {
            float2 pA = up2(accA[rp][jp]), pB = up2(accB[rp][jp]);
            rr[2 * rp][2 * jp]         = pA.x;
            rr[2 * rp + 1][2 * jp + 1] = pA.y;
            rr[2 * rp + 1][2 * jp]     = pB.x;
            rr[2 * rp][2 * jp + 1]     = pB.y;
        }
    const int col = tx * 16;
    float bb[16], gv[16], bv[16];
#pragma unroll
    for (int j = 0; j < 16; j++) {
        bb[j] = bs[col + j] + bn[col + j];
        gv[j] = lng[col + j];
        bv[j] = lnb[col + j];
    }
#pragma unroll
    for (int i = 0; i < 4; i++) {
        float r[16];
        float s1 = 0.f, s2 = 0.f;
#pragma unroll
        for (int j = 0; j < 16; j++) {
            r[j] = fmaxf(rr[i][j] + bb[j], 0.f);
            s1 += r[j];
            s2 += r[j] * r[j];
        }
        // row spans the 8 tx lanes within the warp (lane = (ty%4)*8 + tx)
#pragma unroll
        for (int o = 1; o < 8; o <<= 1) {
            s1 += __shfl_xor_sync(0xffffffffu, s1, o);
            s2 += __shfl_xor_sync(0xffffffffu, s2, o);
        }
        float mean = s1 * (1.0f / 128.0f);
        float var = fmaxf(s2 * (1.0f / 128.0f) - mean * mean, 0.f);
        float inv = rsqrtf(var + 1e-5f);
        int grow = m0 + ty * 4 + i;
        float mk = nmask[grow];
        float o[16];
#pragma unroll
        for (int j = 0; j < 16; j++) o[j] = ((r[j] - mean) * inv * gv[j] + bv[j]) * mk;
#pragma unroll
        for (int q = 0; q < 4; q++)
            *(float4*)&xout[(size_t)grow * HH + col + q * 4] =
                make_float4(o[4 * q], o[4 * q + 1], o[4 * q + 2], o[4 * q + 3]);
    }
}

// ---------------- pool: two-stage ----------------
__global__ void pool_partial_kernel(const float* __restrict__ x, const float* __restrict__ nmask,
                                    float* __restrict__ pp, float* __restrict__ pm) {
    int blk = blockIdx.x;          // 0..255
    int b = blk >> 5, nc = blk & 31;
    int t = threadIdx.x;
    int c = t & 127, half = t >> 7;
    float s = 0.f, mx = -INFINITY;
    for (int i = 0; i < 128; i++) {
        int n = nc * 256 + i * 2 + half;
        float mk = nmask[b * NN + n];
        float v = x[((size_t)(b * NN + n)) * HH + c] * mk;
        s += v;
        if (mk > 0.f) mx = fmaxf(mx, v);
    }
    __shared__ float sh[256];
    sh[t] = s;
    __syncthreads();
    if (half == 0) pp[blk * 128 + c] = sh[c] + sh[c + 128];
    __syncthreads();
    sh[t] = mx;
    __syncthreads();
    if (half == 0) pm[blk * 128 + c] = fmaxf(sh[c], sh[c + 128]);
}

__global__ void pool_final_kernel(const float* __restrict__ pp, const float* __restrict__ pm,
                                  const float* __restrict__ nmask, float* __restrict__ pool) {
    int b = blockIdx.x, c = threadIdx.x;
    float s = 0.f, mx = -INFINITY;
#pragma unroll
    for (int k = 0; k < 32; k++) {
        s += pp[(b * 32 + k) * 128 + c];
        mx = fmaxf(mx, pm[(b * 32 + k) * 128 + c]);
    }
    float cv = 0.f;
    for (int n = c; n < NN; n += 128) cv += nmask[b * NN + n];
    __shared__ float sc[128];
    sc[c] = cv;
    __syncthreads();
    for (int d = 64; d; d >>= 1) {
        if (c < d) sc[c] += sc[c + d];
        __syncthreads();
    }
    float cnt = fmaxf(sc[0], 1.f);
    pool[b * 256 + c] = s / cnt;
    pool[b * 256 + 128 + c] = mx;
}

// ---------------- output MLP ----------------
__global__ void mlp_kernel(const float* __restrict__ pool, const float* __restrict__ W1,
                           const float* __restrict__ b1, const float* __restrict__ W2,
                           const float* __restrict__ b2, float* __restrict__ out) {
    __shared__ float gs[256], hs[128];
    int b = blockIdx.x, tid = threadIdx.x;
    gs[tid] = pool[b * 256 + tid];
    __syncthreads();
    if (tid < 128) {
        float a = b1[tid];
        for (int k = 0; k < 256; k++) a = fmaf(gs[k], W1[k * 128 + tid], a);
        hs[tid] = fmaxf(a, 0.f);
    }
    __syncthreads();
    float a = b2[tid];
    for (int k = 0; k < 128; k++) a = fmaf(hs[k], W2[k * 256 + tid], a);
    out[b * 256 + tid] = a;
}

// ---------------- launch ----------------
extern "C" void kernel_launch(void* const* d_in, const int* in_sizes, int n_in,
                              void* d_out, int out_size) {
    const float* feats = (const float*)d_in[0];
    const int*   ei    = (const int*)d_in[1];
    const float* nmask = (const float*)d_in[2];
    const float* emask = (const float*)d_in[3];
    const float* inW   = (const float*)d_in[4];
    const float* inb   = (const float*)d_in[5];
    const float* sW    = (const float*)d_in[6];
    const float* sb    = (const float*)d_in[7];
    const float* nW    = (const float*)d_in[8];
    const float* nb    = (const float*)d_in[9];
    const float* lng   = (const float*)d_in[10];
    const float* lnb   = (const float*)d_in[11];
    const float* w1    = (const float*)d_in[12];
    const float* b1    = (const float*)d_in[13];
    const float* w2    = (const float*)d_in[14];
    const float* b2    = (const float*)d_in[15];

    float *x0, *x1, *agg, *pool, *cw, *pp, *pm;
    int *cnti, *off, *cur, *csrc, *bsum, *boff;
    cudaGetSymbolAddress((void**)&x0,   g_x0);
    cudaGetSymbolAddress((void**)&x1,   g_x1);
    cudaGetSymbolAddress((void**)&agg,  g_agg);
    cudaGetSymbolAddress((void**)&cnti, g_cnti);
    cudaGetSymbolAddress((void**)&off,  g_off);
    cudaGetSymbolAddress((void**)&cur,  g_cur);
    cudaGetSymbolAddress((void**)&bsum, g_bsum);
    cudaGetSymbolAddress((void**)&boff, g_boff);
    cudaGetSymbolAddress((void**)&csrc, g_csrc);
    cudaGetSymbolAddress((void**)&cw,   g_cw);
    cudaGetSymbolAddress((void**)&pp,   g_pp);
    cudaGetSymbolAddress((void**)&pm,   g_pm);
    cudaGetSymbolAddress((void**)&pool, g_pool);

    dim3 gblk(8, 32);

    // CSR build (once per launch)
    zero4_kernel<<<(MM / 4 + 255) / 256, 256>>>((float4*)cnti, MM / 4);
    count_kernel<<<(ETOT + 255) / 256, 256>>>(ei, emask, cnti);
    psum_kernel<<<64, 1024>>>(cnti, bsum);
    scanb_kernel<<<1, 64>>>(bsum, boff, off);
    emit_kernel<<<64, 1024>>>(cnti, boff, off, cur);
    fill_kernel<<<(ETOT + 255) / 256, 256>>>(ei, emask, cur, csrc, cw);

    // input projection
    input_gemm_kernel<<<MM / 128, gblk>>>(feats, inW, inb, x0);

    float* xin = x0;
    float* xo  = x1;
    for (int l = 0; l < 3; l++) {
        agg_csr_kernel<<<MM * 32 / 256, 256>>>(xin, off, csrc, cw, agg);
        layer_gemm_kernel<<<MM / 128, gblk>>>(xin, agg,
                                              sW + (size_t)l * HH * HH, sb + l * HH,
                                              nW + (size_t)l * HH * HH, nb + l * HH,
                                              lng + l * HH, lnb + l * HH,
                                              nmask, xo);
        float* t = xin; xin = xo; xo = t;
    }

    pool_partial_kernel<<<256, 256>>>(xin, nmask, pp, pm);
    pool_final_kernel<<<BB, 128>>>(pp, pm, nmask, pool);
    mlp_kernel<<<BB, 256>>>(pool, w1, b1, w2, b2, (float*)d_out);
}

// round 5
// speedup vs baseline: 4.0988x; 1.6788x over previous
#include <cuda_runtime.h>
#include <math.h>
#include <stdint.h>

#define BB 8
#define NN 8192
#define EE 65536
#define FIN 64
#define HH 128
#define OUTD 256
#define MM (BB*NN)
#define ETOT (BB*EE)

// ---------------- scratch ----------------
__device__ float g_x0[MM*HH];
__device__ float g_x1[MM*HH];
__device__ float g_agg[MM*HH];
__device__ int   g_cnti[MM];
__device__ int   g_off[MM + 4];
__device__ int   g_cur[MM];
__device__ int   g_bsum[64];
__device__ int   g_boff[64];
__device__ int   g_csrc[ETOT];
__device__ float g_cw[ETOT];
__device__ float g_wt[6*HH*HH];   // transposed weights [l*2+pass][n][k]
__device__ float g_pp[256*128];
__device__ float g_pm[256*128];
__device__ float g_pool[BB*2*HH];

// ---------------- f32x2 packed helpers ----------------
typedef unsigned long long ull;
__device__ __forceinline__ ull pk2(float a, float b) {
    ull r; asm("mov.b64 %0, {%1,%2};" : "=l"(r) : "f"(a), "f"(b)); return r;
}
__device__ __forceinline__ void fma2(ull &d, ull a, ull b) {
    asm("fma.rn.f32x2 %0, %1, %2, %0;" : "+l"(d) : "l"(a), "l"(b));
}
__device__ __forceinline__ float2 up2(ull v) {
    float2 f; asm("mov.b64 {%0,%1}, %2;" : "=f"(f.x), "=f"(f.y) : "l"(v)); return f;
}

// ---------------- tf32 helpers ----------------
__device__ __forceinline__ uint32_t to_tf32(float f) {
    uint32_t r; asm("cvt.rna.tf32.f32 %0, %1;" : "=r"(r) : "f"(f)); return r;
}
__device__ __forceinline__ void mma_tf32(float* c, const uint32_t* a, uint32_t b0, uint32_t b1) {
    asm volatile("mma.sync.aligned.m16n8k8.row.col.f32.tf32.tf32.f32 "
                 "{%0,%1,%2,%3}, {%4,%5,%6,%7}, {%8,%9}, {%0,%1,%2,%3};"
                 : "+f"(c[0]), "+f"(c[1]), "+f"(c[2]), "+f"(c[3])
                 : "r"(a[0]), "r"(a[1]), "r"(a[2]), "r"(a[3]), "r"(b0), "r"(b1));
}

// ---------------- zero helper ----------------
__global__ void zero4_kernel(float4* __restrict__ p, int n4) {
    int i = blockIdx.x * blockDim.x + threadIdx.x;
    if (i < n4) p[i] = make_float4(0.f, 0.f, 0.f, 0.f);
}

// ---------------- CSR build ----------------
__global__ void count_kernel(const int* __restrict__ ei, const float* __restrict__ emask,
                             int* __restrict__ cnti) {
    int e = blockIdx.x * blockDim.x + threadIdx.x;
    if (e >= ETOT) return;
    int b = e / EE, ee = e - b * EE;
    if (emask[e] != 0.f) {
        int tgt = ei[b * 2 * EE + EE + ee] + b * NN;
        atomicAdd(&cnti[tgt], 1);
    }
}

__global__ void psum_kernel(const int* __restrict__ cnt, int* __restrict__ bsum) {
    __shared__ int sh[1024];
    int t = threadIdx.x;
    sh[t] = cnt[blockIdx.x * 1024 + t];
    __syncthreads();
    for (int d = 512; d; d >>= 1) {
        if (t < d) sh[t] += sh[t + d];
        __syncthreads();
    }
    if (t == 0) bsum[blockIdx.x] = sh[0];
}

__global__ void scanb_kernel(const int* __restrict__ bsum, int* __restrict__ boff,
                             int* __restrict__ off) {
    __shared__ int sh[64];
    int t = threadIdx.x;
    int v = bsum[t];
    sh[t] = v;
    __syncthreads();
    for (int d = 1; d < 64; d <<= 1) {
        int u = (t >= d) ? sh[t - d] : 0;
        __syncthreads();
        sh[t] += u;
        __syncthreads();
    }
    boff[t] = sh[t] - v;
    if (t == 63) off[MM] = sh[63];
}

__global__ void emit_kernel(const int* __restrict__ cnt, const int* __restrict__ boff,
                            int* __restrict__ off, int* __restrict__ cur) {
    __shared__ int sh[1024];
    int t = threadIdx.x, g = blockIdx.x * 1024 + t;
    int v = cnt[g];
    sh[t] = v;
    __syncthreads();
    for (int d = 1; d < 1024; d <<= 1) {
        int u = (t >= d) ? sh[t - d] : 0;
        __syncthreads();
        sh[t] += u;
        __syncthreads();
    }
    int ex = sh[t] - v + boff[blockIdx.x];
    off[g] = ex;
    cur[g] = ex;
}

__global__ void fill_kernel(const int* __restrict__ ei, const float* __restrict__ emask,
                            int* __restrict__ cur, int* __restrict__ csrc,
                            float* __restrict__ cw) {
    int e = blockIdx.x * blockDim.x + threadIdx.x;
    if (e >= ETOT) return;
    int b = e / EE, ee = e - b * EE;
    float m = emask[e];
    if (m == 0.f) return;
    int src = ei[b * 2 * EE + ee] + b * NN;
    int tgt = ei[b * 2 * EE + EE + ee] + b * NN;
    int slot = atomicAdd(&cur[tgt], 1);
    csrc[slot] = src;
    cw[slot] = m;
}

// ---------------- weight transpose: wt[n][k] = W[k][n] ----------------
__global__ void wtrans_kernel(const float* __restrict__ sW, const float* __restrict__ nW,
                              float* __restrict__ wt) {
    int mat = blockIdx.x;
    int l = mat >> 1, pass = mat & 1;
    const float* src = (pass ? nW : sW) + (size_t)l * HH * HH;
    float* dst = wt + (size_t)mat * HH * HH;
    for (int idx = threadIdx.x; idx < HH * HH; idx += blockDim.x) {
        int n = idx >> 7, k = idx & 127;
        dst[n * HH + k] = src[k * HH + n];
    }
}

// ---------------- CSR aggregation: warp per node ----------------
__global__ void agg_csr_kernel(const float* __restrict__ x, const int* __restrict__ off,
                               const int* __restrict__ csrc, const float* __restrict__ cw,
                               float* __restrict__ outm) {
    int warp = (blockIdx.x * blockDim.x + threadIdx.x) >> 5;
    int lane = threadIdx.x & 31;
    if (warp >= MM) return;
    int beg = off[warp], end = off[warp + 1];
    float ax = 0.f, ay = 0.f, az = 0.f, aw = 0.f, ws = 0.f;
    int e = beg;
    for (; e + 2 <= end; e += 2) {
        int s0 = csrc[e], s1 = csrc[e + 1];
        float w0 = cw[e], w1 = cw[e + 1];
        float4 v0 = *(const float4*)&x[(size_t)s0 * HH + lane * 4];
        float4 v1 = *(const float4*)&x[(size_t)s1 * HH + lane * 4];
        ax += v0.x * w0 + v1.x * w1;
        ay += v0.y * w0 + v1.y * w1;
        az += v0.z * w0 + v1.z * w1;
        aw += v0.w * w0 + v1.w * w1;
        ws += w0 + w1;
    }
    if (e < end) {
        int s0 = csrc[e];
        float w0 = cw[e];
        float4 v0 = *(const float4*)&x[(size_t)s0 * HH + lane * 4];
        ax += v0.x * w0; ay += v0.y * w0; az += v0.z * w0; aw += v0.w * w0;
        ws += w0;
    }
    float inv = 1.0f / fmaxf(ws, 1.0f);
    *(float4*)&outm[(size_t)warp * HH + lane * 4] =
        make_float4(ax * inv, ay * inv, az * inv, aw * inv);
}

// ---------------- input GEMM (FFMA2, unchanged) ----------------
#define ASTR 130
__global__ void __launch_bounds__(256, 2)
input_gemm_kernel(const float* __restrict__ A, const float* __restrict__ Bw,
                  const float* __restrict__ bias, float* __restrict__ xout) {
    __shared__ __align__(16) float As[32 * ASTR];
    __shared__ __align__(16) float Bs[32 * 128];
    const int tx = threadIdx.x, ty = threadIdx.y;
    const int tid = ty * 8 + tx;
    const int m0 = blockIdx.x * 128;

    ull accA[2][8], accB[2][8];
#pragma unroll
    for (int rp = 0; rp < 2; rp++)
#pragma unroll
        for (int jp = 0; jp < 8; jp++) { accA[rp][jp] = 0ull; accB[rp][jp] = 0ull; }

    for (int k0 = 0; k0 < FIN; k0 += 32) {
#pragma unroll
        for (int p = 0; p < 4; p++) {
            int idx = p * 256 + tid;
            int row = idx >> 3, c4 = idx & 7;
            float4 va = *(const float4*)&A[(size_t)(m0 + row) * FIN + k0 + c4 * 4];
            As[(c4 * 4 + 0) * ASTR + row] = va.x;
            As[(c4 * 4 + 1) * ASTR + row] = va.y;
            As[(c4 * 4 + 2) * ASTR + row] = va.z;
            As[(c4 * 4 + 3) * ASTR + row] = va.w;
        }
#pragma unroll
        for (int p = 0; p < 4; p++) {
            int idx = p * 256 + tid;
            int k = idx >> 5, c4 = idx & 31;
            float4 w4 = *(const float4*)&Bw[(size_t)(k0 + k) * HH + c4 * 4];
            int p4 = c4 ^ (c4 >> 3);
            *(float4*)&Bs[k * 128 + p4 * 4] = w4;
        }
        __syncthreads();
#pragma unroll
        for (int kk = 0; kk < 32; kk++) {
            ull a2[2], a2s[2], b2[8];
            const float* ak = &As[kk * ASTR + ty * 4];
#pragma unroll
            for (int rp = 0; rp < 2; rp++) {
                float2 av = *(const float2*)&ak[2 * rp];
                a2[rp]  = pk2(av.x, av.y);
                a2s[rp] = pk2(av.y, av.x);
            }
            const float* bk = &Bs[kk * 128];
#pragma unroll
            for (int u = 0; u < 4; u++) {
                int c4 = tx * 4 + u;
                int p4 = c4 ^ (c4 >> 3);
                float4 q = *(const float4*)&bk[p4 * 4];
                b2[2 * u]     = pk2(q.x, q.y);
                b2[2 * u + 1] = pk2(q.z, q.w);
            }
#pragma unroll
            for (int rp = 0; rp < 2; rp++)
#pragma unroll
                for (int jp = 0; jp < 8; jp++) {
                    fma2(accA[rp][jp], a2[rp],  b2[jp]);
                    fma2(accB[rp][jp], a2s[rp], b2[jp]);
                }
        }
        __syncthreads();
    }

    float rr[4][16];
#pragma unroll
    for (int rp = 0; rp < 2; rp++)
#pragma unroll
        for (int jp = 0; jp < 8; jp++) {
            float2 pA = up2(accA[rp][jp]), pB = up2(accB[rp][jp]);
            rr[2 * rp][2 * jp]         = pA.x;
            rr[2 * rp + 1][2 * jp + 1] = pA.y;
            rr[2 * rp + 1][2 * jp]     = pB.x;
            rr[2 * rp][2 * jp + 1]     = pB.y;
        }
    const int col = tx * 16;
    float bb[16];
#pragma unroll
    for (int j = 0; j < 16; j++) bb[j] = bias[col + j];
#pragma unroll
    for (int i = 0; i < 4; i++) {
        int grow = m0 + ty * 4 + i;
        float o[16];
#pragma unroll
        for (int j = 0; j < 16; j++) o[j] = fmaxf(rr[i][j] + bb[j], 0.f);
#pragma unroll
        for (int q = 0; q < 4; q++)
            *(float4*)&xout[(size_t)grow * HH + col + q * 4] =
                make_float4(o[4 * q], o[4 * q + 1], o[4 * q + 2], o[4 * q + 3]);
    }
}

// ================= HMMA tf32 fused layer =================
// CTA 128x128, 256 threads, warps: 4(M) x 2(N); warp tile 32(M) x 64(N).
// mma.m16n8k8: per warp 2 m-subtiles x 8 n-subtiles. K = 2 passes x 128, chunks of 32.
#define LSTR 36
__global__ void __launch_bounds__(256, 2)
layer_mma_kernel(const float* __restrict__ x, const float* __restrict__ agg,
                 const float* __restrict__ Wst, const float* __restrict__ Wnt,
                 const float* __restrict__ bsb, const float* __restrict__ bnb,
                 const float* __restrict__ lng, const float* __restrict__ lnb,
                 const float* __restrict__ nmask, float* __restrict__ xout) {
    __shared__ __align__(16) uint32_t As[128 * LSTR];
    __shared__ __align__(16) uint32_t Bs[128 * LSTR];
    __shared__ float red[128][4];

    const int tid = threadIdx.x;
    const int wid = tid >> 5, lane = tid & 31;
    const int wm = wid & 3, wn = wid >> 2;    // 4 M-warps, 2 N-warps
    const int g = lane >> 2, t = lane & 3;
    const int m0 = blockIdx.x * 128;

    float acc[2][8][4];
#pragma unroll
    for (int mi = 0; mi < 2; mi++)
#pragma unroll
        for (int ni = 0; ni < 8; ni++)
#pragma unroll
            for (int c = 0; c < 4; c++) acc[mi][ni][c] = 0.f;

    for (int pass = 0; pass < 2; ++pass) {
        const float* Asrc = (pass ? agg : x) + (size_t)m0 * HH;
        const float* Bsrc = pass ? Wnt : Wst;
        for (int k0 = 0; k0 < HH; k0 += 32) {
            __syncthreads();
            // stage A (m-major) and B (n-major), tf32-converted, stride LSTR
#pragma unroll
            for (int u = 0; u < 4; u++) {
                int idx = u * 256 + tid;
                int row = idx >> 3, c4 = idx & 7;
                float4 va = *(const float4*)&Asrc[(size_t)row * HH + k0 + c4 * 4];
                uint4 ta = make_uint4(to_tf32(va.x), to_tf32(va.y), to_tf32(va.z), to_tf32(va.w));
                *(uint4*)&As[row * LSTR + c4 * 4] = ta;
                float4 vb = *(const float4*)&Bsrc[(size_t)row * HH + k0 + c4 * 4];
                uint4 tb = make_uint4(to_tf32(vb.x), to_tf32(vb.y), to_tf32(vb.z), to_tf32(vb.w));
                *(uint4*)&Bs[row * LSTR + c4 * 4] = tb;
            }
            __syncthreads();
#pragma unroll
            for (int ks = 0; ks < 4; ks++) {
                uint32_t a[2][4], b[8][2];
#pragma unroll
                for (int mi = 0; mi < 2; mi++) {
                    int base = (wm * 32 + mi * 16 + g) * LSTR + ks * 8 + t;
                    a[mi][0] = As[base];
                    a[mi][1] = As[base + 8 * LSTR];
                    a[mi][2] = As[base + 4];
                    a[mi][3] = As[base + 8 * LSTR + 4];
                }
#pragma unroll
                for (int ni = 0; ni < 8; ni++) {
                    int nb = (wn * 64 + ni * 8 + g) * LSTR + ks * 8 + t;
                    b[ni][0] = Bs[nb];
                    b[ni][1] = Bs[nb + 4];
                }
#pragma unroll
                for (int mi = 0; mi < 2; mi++)
#pragma unroll
                    for (int ni = 0; ni < 8; ni++)
                        mma_tf32(acc[mi][ni], a[mi], b[ni][0], b[ni][1]);
            }
        }
    }

    // ---- epilogue: bias + relu + layernorm + mask ----
    // thread's columns: col(ni,j) = wn*64 + ni*8 + 2t + j
    float cb[16], cgv[16], cbv[16];
#pragma unroll
    for (int ni = 0; ni < 8; ni++)
#pragma unroll
        for (int j = 0; j < 2; j++) {
            int c = wn * 64 + ni * 8 + 2 * t + j;
            cb[ni * 2 + j]  = bsb[c] + bnb[c];
            cgv[ni * 2 + j] = lng[c];
            cbv[ni * 2 + j] = lnb[c];
        }
    // bias+relu, per-row partial sums reduced over t (xor 1, 2)
#pragma unroll
    for (int mi = 0; mi < 2; mi++)
#pragma unroll
        for (int h = 0; h < 2; h++) {
            float s1 = 0.f, s2 = 0.f;
#pragma unroll
            for (int ni = 0; ni < 8; ni++)
#pragma unroll
                for (int j = 0; j < 2; j++) {
                    float v = fmaxf(acc[mi][ni][2 * h + j] + cb[ni * 2 + j], 0.f);
                    acc[mi][ni][2 * h + j] = v;
                    s1 += v;
                    s2 += v * v;
                }
            s1 += __shfl_xor_sync(0xffffffffu, s1, 1);
            s1 += __shfl_xor_sync(0xffffffffu, s1, 2);
            s2 += __shfl_xor_sync(0xffffffffu, s2, 1);
            s2 += __shfl_xor_sync(0xffffffffu, s2, 2);
            if (t == 0) {
                int row = wm * 32 + mi * 16 + g + 8 * h;
                red[row][wn * 2]     = s1;
                red[row][wn * 2 + 1] = s2;
            }
        }
    __syncthreads();
#pragma unroll
    for (int mi = 0; mi < 2; mi++)
#pragma unroll
        for (int h = 0; h < 2; h++) {
            int row = wm * 32 + mi * 16 + g + 8 * h;
            float s1 = red[row][0] + red[row][2];
            float s2 = red[row][1] + red[row][3];
            float mean = s1 * (1.0f / 128.0f);
            float var = fmaxf(s2 * (1.0f / 128.0f) - mean * mean, 0.f);
            float inv = rsqrtf(var + 1e-5f);
            int grow = m0 + row;
            float mk = nmask[grow];
#pragma unroll
            for (int ni = 0; ni < 8; ni++) {
                float2 o;
                o.x = ((acc[mi][ni][2 * h]     - mean) * inv * cgv[ni * 2]     + cbv[ni * 2])     * mk;
                o.y = ((acc[mi][ni][2 * h + 1] - mean) * inv * cgv[ni * 2 + 1] + cbv[ni * 2 + 1]) * mk;
                *(float2*)&xout[(size_t)grow * HH + wn * 64 + ni * 8 + 2 * t] = o;
            }
        }
}

// ---------------- pool: two-stage ----------------
__global__ void pool_partial_kernel(const float* __restrict__ x, const float* __restrict__ nmask,
                                    float* __restrict__ pp, float* __restrict__ pm) {
    int blk = blockIdx.x;
    int b = blk >> 5, nc = blk & 31;
    int t = threadIdx.x;
    int c = t & 127, half = t >> 7;
    float s = 0.f, mx = -INFINITY;
    for (int i = 0; i < 128; i++) {
        int n = nc * 256 + i * 2 + half;
        float mk = nmask[b * NN + n];
        float v = x[((size_t)(b * NN + n)) * HH + c] * mk;
        s += v;
        if (mk > 0.f) mx = fmaxf(mx, v);
    }
    __shared__ float sh[256];
    sh[t] = s;
    __syncthreads();
    if (half == 0) pp[blk * 128 + c] = sh[c] + sh[c + 128];
    __syncthreads();
    sh[t] = mx;
    __syncthreads();
    if (half == 0) pm[blk * 128 + c] = fmaxf(sh[c], sh[c + 128]);
}

__global__ void pool_final_kernel(const float* __restrict__ pp, const float* __restrict__ pm,
                                  const float* __restrict__ nmask, float* __restrict__ pool) {
    int b = blockIdx.x, c = threadIdx.x;
    float s = 0.f, mx = -INFINITY;
#pragma unroll
    for (int k = 0; k < 32; k++) {
        s += pp[(b * 32 + k) * 128 + c];
        mx = fmaxf(mx, pm[(b * 32 + k) * 128 + c]);
    }
    float cv = 0.f;
    for (int n = c; n < NN; n += 128) cv += nmask[b * NN + n];
    __shared__ float sc[128];
    sc[c] = cv;
    __syncthreads();
    for (int d = 64; d; d >>= 1) {
        if (c < d) sc[c] += sc[c + d];
        __syncthreads();
    }
    float cnt = fmaxf(sc[0], 1.f);
    pool[b * 256 + c] = s / cnt;
    pool[b * 256 + 128 + c] = mx;
}

// ---------------- output MLP ----------------
__global__ void mlp_kernel(const float* __restrict__ pool, const float* __restrict__ W1,
                           const float* __restrict__ b1, const float* __restrict__ W2,
                           const float* __restrict__ b2, float* __restrict__ out) {
    __shared__ float gs[256], hs[128];
    int b = blockIdx.x, tid = threadIdx.x;
    gs[tid] = pool[b * 256 + tid];
    __syncthreads();
    if (tid < 128) {
        float a = b1[tid];
        for (int k = 0; k < 256; k++) a = fmaf(gs[k], W1[k * 128 + tid], a);
        hs[tid] = fmaxf(a, 0.f);
    }
    __syncthreads();
    float a = b2[tid];
    for (int k = 0; k < 128; k++) a = fmaf(hs[k], W2[k * 256 + tid], a);
    out[b * 256 + tid] = a;
}

// ---------------- launch ----------------
extern "C" void kernel_launch(void* const* d_in, const int* in_sizes, int n_in,
                              void* d_out, int out_size) {
    const float* feats = (const float*)d_in[0];
    const int*   ei    = (const int*)d_in[1];
    const float* nmask = (const float*)d_in[2];
    const float* emask = (const float*)d_in[3];
    const float* inW   = (const float*)d_in[4];
    const float* inb   = (const float*)d_in[5];
    const float* sW    = (const float*)d_in[6];
    const float* sb    = (const float*)d_in[7];
    const float* nW    = (const float*)d_in[8];
    const float* nb    = (const float*)d_in[9];
    const float* lng   = (const float*)d_in[10];
    const float* lnb   = (const float*)d_in[11];
    const float* w1    = (const float*)d_in[12];
    const float* b1    = (const float*)d_in[13];
    const float* w2    = (const float*)d_in[14];
    const float* b2    = (const float*)d_in[15];

    float *x0, *x1, *agg, *pool, *cw, *pp, *pm, *wt;
    int *cnti, *off, *cur, *csrc, *bsum, *boff;
    cudaGetSymbolAddress((void**)&x0,   g_x0);
    cudaGetSymbolAddress((void**)&x1,   g_x1);
    cudaGetSymbolAddress((void**)&agg,  g_agg);
    cudaGetSymbolAddress((void**)&cnti, g_cnti);
    cudaGetSymbolAddress((void**)&off,  g_off);
    cudaGetSymbolAddress((void**)&cur,  g_cur);
    cudaGetSymbolAddress((void**)&bsum, g_bsum);
    cudaGetSymbolAddress((void**)&boff, g_boff);
    cudaGetSymbolAddress((void**)&csrc, g_csrc);
    cudaGetSymbolAddress((void**)&cw,   g_cw);
    cudaGetSymbolAddress((void**)&wt,   g_wt);
    cudaGetSymbolAddress((void**)&pp,   g_pp);
    cudaGetSymbolAddress((void**)&pm,   g_pm);
    cudaGetSymbolAddress((void**)&pool, g_pool);

    dim3 gblk(8, 32);

    // CSR build + weight transpose (once per launch)
    zero4_kernel<<<(MM / 4 + 255) / 256, 256>>>((float4*)cnti, MM / 4);
    count_kernel<<<(ETOT + 255) / 256, 256>>>(ei, emask, cnti);
    psum_kernel<<<64, 1024>>>(cnti, bsum);
    scanb_kernel<<<1, 64>>>(bsum, boff, off);
    emit_kernel<<<64, 1024>>>(cnti, boff, off, cur);
    fill_kernel<<<(ETOT + 255) / 256, 256>>>(ei, emask, cur, csrc, cw);
    wtrans_kernel<<<6, 256>>>(sW, nW, wt);

    // input projection
    input_gemm_kernel<<<MM / 128, gblk>>>(feats, inW, inb, x0);

    float* xin = x0;
    float* xo  = x1;
    for (int l = 0; l < 3; l++) {
        agg_csr_kernel<<<MM * 32 / 256, 256>>>(xin, off, csrc, cw, agg);
        layer_mma_kernel<<<MM / 128, 256>>>(xin, agg,
                                            wt + (size_t)(l * 2) * HH * HH,
                                            wt + (size_t)(l * 2 + 1) * HH * HH,
                                            sb + l * HH, nb + l * HH,
                                            lng + l * HH, lnb + l * HH,
                                            nmask, xo);
        float* t = xin; xin = xo; xo = t;
    }

    pool_partial_kernel<<<256, 256>>>(xin, nmask, pp, pm);
    pool_final_kernel<<<BB, 128>>>(pp, pm, nmask, pool);
    mlp_kernel<<<BB, 256>>>(pool, w1, b1, w2, b2, (float*)d_out);
}

// round 6
// speedup vs baseline: 4.1238x; 1.0061x over previous
#include <cuda_runtime.h>
#include <math.h>
#include <stdint.h>

#define BB 8
#define NN 8192
#define EE 65536
#define FIN 64
#define HH 128
#define OUTD 256
#define MM (BB*NN)
#define ETOT (BB*EE)

// ---------------- scratch ----------------
__device__ float g_x0[MM*HH];
__device__ float g_x1[MM*HH];
__device__ float g_agg[MM*HH];
__device__ int   g_cnti[MM];
__device__ int   g_off[MM + 4];
__device__ int   g_cur[MM];
__device__ int   g_bsum[64];
__device__ int   g_csrc[ETOT];
__device__ float g_cw[ETOT];
__device__ float g_wt[6*HH*HH + HH*FIN];  // [l*2+pass][n][k], then inW^T [n][k]
__device__ float g_pp[256*128];
__device__ float g_pm[256*128];
__device__ float g_pool[BB*2*HH];

// ---------------- tf32 helpers ----------------
__device__ __forceinline__ uint32_t to_tf32(float f) {
    uint32_t r; asm("cvt.rna.tf32.f32 %0, %1;" : "=r"(r) : "f"(f)); return r;
}
__device__ __forceinline__ void mma_tf32(float* c, const uint32_t* a, uint32_t b0, uint32_t b1) {
    asm volatile("mma.sync.aligned.m16n8k8.row.col.f32.tf32.tf32.f32 "
                 "{%0,%1,%2,%3}, {%4,%5,%6,%7}, {%8,%9}, {%0,%1,%2,%3};"
                 : "+f"(c[0]), "+f"(c[1]), "+f"(c[2]), "+f"(c[3])
                 : "r"(a[0]), "r"(a[1]), "r"(a[2]), "r"(a[3]), "r"(b0), "r"(b1));
}

// ---------------- zero helper ----------------
__global__ void zero4_kernel(float4* __restrict__ p, int n4) {
    int i = blockIdx.x * blockDim.x + threadIdx.x;
    if (i < n4) p[i] = make_float4(0.f, 0.f, 0.f, 0.f);
}

// ---------------- CSR build ----------------
__global__ void count_kernel(const int* __restrict__ ei, const float* __restrict__ emask,
                             int* __restrict__ cnti) {
    int e = blockIdx.x * blockDim.x + threadIdx.x;
    if (e >= ETOT) return;
    int b = e / EE, ee = e - b * EE;
    if (emask[e] != 0.f) {
        int tgt = ei[b * 2 * EE + EE + ee] + b * NN;
        atomicAdd(&cnti[tgt], 1);
    }
}

__global__ void psum_kernel(const int* __restrict__ cnt, int* __restrict__ bsum) {
    __shared__ int sh[1024];
    int t = threadIdx.x;
    sh[t] = cnt[blockIdx.x * 1024 + t];
    __syncthreads();
    for (int d = 512; d; d >>= 1) {
        if (t < d) sh[t] += sh[t + d];
        __syncthreads();
    }
    if (t == 0) bsum[blockIdx.x] = sh[0];
}

// emit: per-block exclusive scan + inline scan of the 64 block sums
__global__ void emit_kernel(const int* __restrict__ cnt, const int* __restrict__ bsum,
                            int* __restrict__ off, int* __restrict__ cur) {
    __shared__ int sh[1024];
    __shared__ int bpre, btot;
    int t = threadIdx.x, g = blockIdx.x * 1024 + t;
    int v = cnt[g];
    sh[t] = v;
    if (t == 0) {
        int p = 0, tot = 0;
        for (int i = 0; i < 64; i++) {
            int s = bsum[i];
            if (i < blockIdx.x) p += s;
            tot += s;
        }
        bpre = p;
        btot = tot;
    }
    __syncthreads();
    for (int d = 1; d < 1024; d <<= 1) {
        int u = (t >= d) ? sh[t - d] : 0;
        __syncthreads();
        sh[t] += u;
        __syncthreads();
    }
    int ex = sh[t] - v + bpre;
    off[g] = ex;
    cur[g] = ex;
    if (blockIdx.x == 63 && t == 1023) off[MM] = btot;
}

__global__ void fill_kernel(const int* __restrict__ ei, const float* __restrict__ emask,
                            int* __restrict__ cur, int* __restrict__ csrc,
                            float* __restrict__ cw) {
    int e = blockIdx.x * blockDim.x + threadIdx.x;
    if (e >= ETOT) return;
    int b = e / EE, ee = e - b * EE;
    float m = emask[e];
    if (m == 0.f) return;
    int src = ei[b * 2 * EE + ee] + b * NN;
    int tgt = ei[b * 2 * EE + EE + ee] + b * NN;
    int slot = atomicAdd(&cur[tgt], 1);
    csrc[slot] = src;
    cw[slot] = m;
}

// ---------------- weight transpose ----------------
// mats 0..5: wt[n][k] = W[k][n] (128x128). mat 6: inW^T [n][k] (128x64).
__global__ void wtrans_kernel(const float* __restrict__ sW, const float* __restrict__ nW,
                              const float* __restrict__ inW, float* __restrict__ wt) {
    int mat = blockIdx.x;
    if (mat < 6) {
        int l = mat >> 1, pass = mat & 1;
        const float* src = (pass ? nW : sW) + (size_t)l * HH * HH;
        float* dst = wt + (size_t)mat * HH * HH;
        for (int idx = threadIdx.x; idx < HH * HH; idx += blockDim.x) {
            int n = idx >> 7, k = idx & 127;
            dst[n * HH + k] = src[k * HH + n];
        }
    } else {
        float* dst = wt + (size_t)6 * HH * HH;
        for (int idx = threadIdx.x; idx < HH * FIN; idx += blockDim.x) {
            int n = idx >> 6, k = idx & 63;
            dst[n * FIN + k] = inW[k * HH + n];
        }
    }
}

// ---------------- CSR aggregation: warp per node ----------------
__global__ void agg_csr_kernel(const float* __restrict__ x, const int* __restrict__ off,
                               const int* __restrict__ csrc, const float* __restrict__ cw,
                               float* __restrict__ outm) {
    int warp = (blockIdx.x * blockDim.x + threadIdx.x) >> 5;
    int lane = threadIdx.x & 31;
    if (warp >= MM) return;
    int beg = off[warp], end = off[warp + 1];
    float ax = 0.f, ay = 0.f, az = 0.f, aw = 0.f, ws = 0.f;
    int e = beg;
    for (; e + 2 <= end; e += 2) {
        int s0 = csrc[e], s1 = csrc[e + 1];
        float w0 = cw[e], w1 = cw[e + 1];
        float4 v0 = *(const float4*)&x[(size_t)s0 * HH + lane * 4];
        float4 v1 = *(const float4*)&x[(size_t)s1 * HH + lane * 4];
        ax += v0.x * w0 + v1.x * w1;
        ay += v0.y * w0 + v1.y * w1;
        az += v0.z * w0 + v1.z * w1;
        aw += v0.w * w0 + v1.w * w1;
        ws += w0 + w1;
    }
    if (e < end) {
        int s0 = csrc[e];
        float w0 = cw[e];
        float4 v0 = *(const float4*)&x[(size_t)s0 * HH + lane * 4];
        ax += v0.x * w0; ay += v0.y * w0; az += v0.z * w0; aw += v0.w * w0;
        ws += w0;
    }
    float inv = 1.0f / fmaxf(ws, 1.0f);
    *(float4*)&outm[(size_t)warp * HH + lane * 4] =
        make_float4(ax * inv, ay * inv, az * inv, aw * inv);
}

// ================= HMMA tf32 input GEMM =================
// CTA 128x128, warps 4(M) x 2(N); warp tile 32x64; K=64 (2 chunks of 32).
#define LSTR 36
__global__ void __launch_bounds__(256, 2)
input_mma_kernel(const float* __restrict__ A, const float* __restrict__ Wt,
                 const float* __restrict__ bias, float* __restrict__ xout) {
    __shared__ __align__(16) uint32_t As[128 * LSTR];
    __shared__ __align__(16) uint32_t Bs[128 * LSTR];

    const int tid = threadIdx.x;
    const int wid = tid >> 5, lane = tid & 31;
    const int wm = wid & 3, wn = wid >> 2;
    const int g = lane >> 2, t = lane & 3;
    const int m0 = blockIdx.x * 128;

    float acc[2][8][4];
#pragma unroll
    for (int mi = 0; mi < 2; mi++)
#pragma unroll
        for (int ni = 0; ni < 8; ni++)
#pragma unroll
            for (int c = 0; c < 4; c++) acc[mi][ni][c] = 0.f;

    const float* Asrc = A + (size_t)m0 * FIN;
    float4 pva[4], pvb[4];
    // prefetch chunk 0
#pragma unroll
    for (int u = 0; u < 4; u++) {
        int idx = u * 256 + tid;
        int row = idx >> 3, c4 = idx & 7;
        pva[u] = *(const float4*)&Asrc[(size_t)row * FIN + c4 * 4];
        pvb[u] = *(const float4*)&Wt[(size_t)row * FIN + c4 * 4];
    }
#pragma unroll 1
    for (int ch = 0; ch < 2; ch++) {
        __syncthreads();
#pragma unroll
        for (int u = 0; u < 4; u++) {
            int idx = u * 256 + tid;
            int row = idx >> 3, c4 = idx & 7;
            *(uint4*)&As[row * LSTR + c4 * 4] =
                make_uint4(to_tf32(pva[u].x), to_tf32(pva[u].y), to_tf32(pva[u].z), to_tf32(pva[u].w));
            *(uint4*)&Bs[row * LSTR + c4 * 4] =
                make_uint4(to_tf32(pvb[u].x), to_tf32(pvb[u].y), to_tf32(pvb[u].z), to_tf32(pvb[u].w));
        }
        __syncthreads();
        if (ch == 0) {
#pragma unroll
            for (int u = 0; u < 4; u++) {
                int idx = u * 256 + tid;
                int row = idx >> 3, c4 = idx & 7;
                pva[u] = *(const float4*)&Asrc[(size_t)row * FIN + 32 + c4 * 4];
                pvb[u] = *(const float4*)&Wt[(size_t)row * FIN + 32 + c4 * 4];
            }
        }
#pragma unroll
        for (int ks = 0; ks < 4; ks++) {
            uint32_t a[2][4], b[8][2];
#pragma unroll
            for (int mi = 0; mi < 2; mi++) {
                int base = (wm * 32 + mi * 16 + g) * LSTR + ks * 8 + t;
                a[mi][0] = As[base];
                a[mi][1] = As[base + 8 * LSTR];
                a[mi][2] = As[base + 4];
                a[mi][3] = As[base + 8 * LSTR + 4];
            }
#pragma unroll
            for (int ni = 0; ni < 8; ni++) {
                int nb = (wn * 64 + ni * 8 + g) * LSTR + ks * 8 + t;
                b[ni][0] = Bs[nb];
                b[ni][1] = Bs[nb + 4];
            }
#pragma unroll
            for (int mi = 0; mi < 2; mi++)
#pragma unroll
                for (int ni = 0; ni < 8; ni++)
                    mma_tf32(acc[mi][ni], a[mi], b[ni][0], b[ni][1]);
        }
    }

    // epilogue: bias + relu
    float cb[16];
#pragma unroll
    for (int ni = 0; ni < 8; ni++)
#pragma unroll
        for (int j = 0; j < 2; j++)
            cb[ni * 2 + j] = bias[wn * 64 + ni * 8 + 2 * t + j];
#pragma unroll
    for (int mi = 0; mi < 2; mi++)
#pragma unroll
        for (int h = 0; h < 2; h++) {
            int grow = m0 + wm * 32 + mi * 16 + g + 8 * h;
#pragma unroll
            for (int ni = 0; ni < 8; ni++) {
                float2 o;
                o.x = fmaxf(acc[mi][ni][2 * h]     + cb[ni * 2],     0.f);
                o.y = fmaxf(acc[mi][ni][2 * h + 1] + cb[ni * 2 + 1], 0.f);
                *(float2*)&xout[(size_t)grow * HH + wn * 64 + ni * 8 + 2 * t] = o;
            }
        }
}

// ================= HMMA tf32 fused layer =================
__global__ void __launch_bounds__(256, 2)
layer_mma_kernel(const float* __restrict__ x, const float* __restrict__ agg,
                 const float* __restrict__ Wst, const float* __restrict__ Wnt,
                 const float* __restrict__ bsb, const float* __restrict__ bnb,
                 const float* __restrict__ lng, const float* __restrict__ lnb,
                 const float* __restrict__ nmask, float* __restrict__ xout) {
    __shared__ __align__(16) uint32_t As[128 * LSTR];
    __shared__ __align__(16) uint32_t Bs[128 * LSTR];
    __shared__ float red[128][4];

    const int tid = threadIdx.x;
    const int wid = tid >> 5, lane = tid & 31;
    const int wm = wid & 3, wn = wid >> 2;
    const int g = lane >> 2, t = lane & 3;
    const int m0 = blockIdx.x * 128;

    float acc[2][8][4];
#pragma unroll
    for (int mi = 0; mi < 2; mi++)
#pragma unroll
        for (int ni = 0; ni < 8; ni++)
#pragma unroll
            for (int c = 0; c < 4; c++) acc[mi][ni][c] = 0.f;

    const float* Apass[2] = {x + (size_t)m0 * HH, agg + (size_t)m0 * HH};
    const float* Bpass[2] = {Wst, Wnt};

    float4 pva[4], pvb[4];
    // prefetch chunk 0
#pragma unroll
    for (int u = 0; u < 4; u++) {
        int idx = u * 256 + tid;
        int row = idx >> 3, c4 = idx & 7;
        pva[u] = *(const float4*)&Apass[0][(size_t)row * HH + c4 * 4];
        pvb[u] = *(const float4*)&Bpass[0][(size_t)row * HH + c4 * 4];
    }
#pragma unroll 1
    for (int ch = 0; ch < 8; ch++) {
        __syncthreads();
#pragma unroll
        for (int u = 0; u < 4; u++) {
            int idx = u * 256 + tid;
            int row = idx >> 3, c4 = idx & 7;
            *(uint4*)&As[row * LSTR + c4 * 4] =
                make_uint4(to_tf32(pva[u].x), to_tf32(pva[u].y), to_tf32(pva[u].z), to_tf32(pva[u].w));
            *(uint4*)&Bs[row * LSTR + c4 * 4] =
                make_uint4(to_tf32(pvb[u].x), to_tf32(pvb[u].y), to_tf32(pvb[u].z), to_tf32(pvb[u].w));
        }
        __syncthreads();
        if (ch < 7) {
            int nc = ch + 1;
            const float* A_ = Apass[nc >> 2];
            const float* B_ = Bpass[nc >> 2];
            int k0 = (nc & 3) * 32;
#pragma unroll
            for (int u = 0; u < 4; u++) {
                int idx = u * 256 + tid;
                int row = idx >> 3, c4 = idx & 7;
                pva[u] = *(const float4*)&A_[(size_t)row * HH + k0 + c4 * 4];
                pvb[u] = *(const float4*)&B_[(size_t)row * HH + k0 + c4 * 4];
            }
        }
#pragma unroll
        for (int ks = 0; ks < 4; ks++) {
            uint32_t a[2][4], b[8][2];
#pragma unroll
            for (int mi = 0; mi < 2; mi++) {
                int base = (wm * 32 + mi * 16 + g) * LSTR + ks * 8 + t;
                a[mi][0] = As[base];
                a[mi][1] = As[base + 8 * LSTR];
                a[mi][2] = As[base + 4];
                a[mi][3] = As[base + 8 * LSTR + 4];
            }
#pragma unroll
            for (int ni = 0; ni < 8; ni++) {
                int nb = (wn * 64 + ni * 8 + g) * LSTR + ks * 8 + t;
                b[ni][0] = Bs[nb];
                b[ni][1] = Bs[nb + 4];
            }
#pragma unroll
            for (int mi = 0; mi < 2; mi++)
#pragma unroll
                for (int ni = 0; ni < 8; ni++)
                    mma_tf32(acc[mi][ni], a[mi], b[ni][0], b[ni][1]);
        }
    }

    // ---- epilogue: bias + relu + layernorm + mask ----
    float cb[16], cgv[16], cbv[16];
#pragma unroll
    for (int ni = 0; ni < 8; ni++)
#pragma unroll
        for (int j = 0; j < 2; j++) {
            int c = wn * 64 + ni * 8 + 2 * t + j;
            cb[ni * 2 + j]  = bsb[c] + bnb[c];
            cgv[ni * 2 + j] = lng[c];
            cbv[ni * 2 + j] = lnb[c];
        }
#pragma unroll
    for (int mi = 0; mi < 2; mi++)
#pragma unroll
        for (int h = 0; h < 2; h++) {
            float s1 = 0.f, s2 = 0.f;
#pragma unroll
            for (int ni = 0; ni < 8; ni++)
#pragma unroll
                for (int j = 0; j < 2; j++) {
                    float v = fmaxf(acc[mi][ni][2 * h + j] + cb[ni * 2 + j], 0.f);
                    acc[mi][ni][2 * h + j] = v;
                    s1 += v;
                    s2 += v * v;
                }
            s1 += __shfl_xor_sync(0xffffffffu, s1, 1);
            s1 += __shfl_xor_sync(0xffffffffu, s1, 2);
            s2 += __shfl_xor_sync(0xffffffffu, s2, 1);
            s2 += __shfl_xor_sync(0xffffffffu, s2, 2);
            if (t == 0) {
                int row = wm * 32 + mi * 16 + g + 8 * h;
                red[row][wn * 2]     = s1;
                red[row][wn * 2 + 1] = s2;
            }
        }
    __syncthreads();
#pragma unroll
    for (int mi = 0; mi < 2; mi++)
#pragma unroll
        for (int h = 0; h < 2; h++) {
            int row = wm * 32 + mi * 16 + g + 8 * h;
            float s1 = red[row][0] + red[row][2];
            float s2 = red[row][1] + red[row][3];
            float mean = s1 * (1.0f / 128.0f);
            float var = fmaxf(s2 * (1.0f / 128.0f) - mean * mean, 0.f);
            float inv = rsqrtf(var + 1e-5f);
            int grow = m0 + row;
            float mk = nmask[grow];
#pragma unroll
            for (int ni = 0; ni < 8; ni++) {
                float2 o;
                o.x = ((acc[mi][ni][2 * h]     - mean) * inv * cgv[ni * 2]     + cbv[ni * 2])     * mk;
                o.y = ((acc[mi][ni][2 * h + 1] - mean) * inv * cgv[ni * 2 + 1] + cbv[ni * 2 + 1]) * mk;
                *(float2*)&xout[(size_t)grow * HH + wn * 64 + ni * 8 + 2 * t] = o;
            }
        }
}

// ---------------- pool: two-stage ----------------
__global__ void pool_partial_kernel(const float* __restrict__ x, const float* __restrict__ nmask,
                                    float* __restrict__ pp, float* __restrict__ pm) {
    int blk = blockIdx.x;
    int b = blk >> 5, nc = blk & 31;
    int t = threadIdx.x;
    int c = t & 127, half = t >> 7;
    float s = 0.f, mx = -INFINITY;
    for (int i = 0; i < 128; i++) {
        int n = nc * 256 + i * 2 + half;
        float mk = nmask[b * NN + n];
        float v = x[((size_t)(b * NN + n)) * HH + c] * mk;
        s += v;
        if (mk > 0.f) mx = fmaxf(mx, v);
    }
    __shared__ float sh[256];
    sh[t] = s;
    __syncthreads();
    if (half == 0) pp[blk * 128 + c] = sh[c] + sh[c + 128];
    __syncthreads();
    sh[t] = mx;
    __syncthreads();
    if (half == 0) pm[blk * 128 + c] = fmaxf(sh[c], sh[c + 128]);
}

__global__ void pool_final_kernel(const float* __restrict__ pp, const float* __restrict__ pm,
                                  const float* __restrict__ nmask, float* __restrict__ pool) {
    int b = blockIdx.x, c = threadIdx.x;
    float s = 0.f, mx = -INFINITY;
#pragma unroll
    for (int k = 0; k < 32; k++) {
        s += pp[(b * 32 + k) * 128 + c];
        mx = fmaxf(mx, pm[(b * 32 + k) * 128 + c]);
    }
    float cv = 0.f;
    for (int n = c; n < NN; n += 128) cv += nmask[b * NN + n];
    __shared__ float sc[128];
    sc[c] = cv;
    __syncthreads();
    for (int d = 64; d; d >>= 1) {
        if (c < d) sc[c] += sc[c + d];
        __syncthreads();
    }
    float cnt = fmaxf(sc[0], 1.f);
    pool[b * 256 + c] = s / cnt;
    pool[b * 256 + 128 + c] = mx;
}

// ---------------- output MLP ----------------
__global__ void mlp_kernel(const float* __restrict__ pool, const float* __restrict__ W1,
                           const float* __restrict__ b1, const float* __restrict__ W2,
                           const float* __restrict__ b2, float* __restrict__ out) {
    __shared__ float gs[256], hs[128];
    int b = blockIdx.x, tid = threadIdx.x;
    gs[tid] = pool[b * 256 + tid];
    __syncthreads();
    if (tid < 128) {
        float a = b1[tid];
        for (int k = 0; k < 256; k++) a = fmaf(gs[k], W1[k * 128 + tid], a);
        hs[tid] = fmaxf(a, 0.f);
    }
    __syncthreads();
    float a = b2[tid];
    for (int k = 0; k < 128; k++) a = fmaf(hs[k], W2[k * 256 + tid], a);
    out[b * 256 + tid] = a;
}

// ---------------- launch ----------------
extern "C" void kernel_launch(void* const* d_in, const int* in_sizes, int n_in,
                              void* d_out, int out_size) {
    const float* feats = (const float*)d_in[0];
    const int*   ei    = (const int*)d_in[1];
    const float* nmask = (const float*)d_in[2];
    const float* emask = (const float*)d_in[3];
    const float* inW   = (const float*)d_in[4];
    const float* inb   = (const float*)d_in[5];
    const float* sW    = (const float*)d_in[6];
    const float* sb    = (const float*)d_in[7];
    const float* nW    = (const float*)d_in[8];
    const float* nb    = (const float*)d_in[9];
    const float* lng   = (const float*)d_in[10];
    const float* lnb   = (const float*)d_in[11];
    const float* w1    = (const float*)d_in[12];
    const float* b1    = (const float*)d_in[13];
    const float* w2    = (const float*)d_in[14];
    const float* b2    = (const float*)d_in[15];

    float *x0, *x1, *agg, *pool, *cw, *pp, *pm, *wt;
    int *cnti, *off, *cur, *csrc, *bsum;
    cudaGetSymbolAddress((void**)&x0,   g_x0);
    cudaGetSymbolAddress((void**)&x1,   g_x1);
    cudaGetSymbolAddress((void**)&agg,  g_agg);
    cudaGetSymbolAddress((void**)&cnti, g_cnti);
    cudaGetSymbolAddress((void**)&off,  g_off);
    cudaGetSymbolAddress((void**)&cur,  g_cur);
    cudaGetSymbolAddress((void**)&bsum, g_bsum);
    cudaGetSymbolAddress((void**)&csrc, g_csrc);
    cudaGetSymbolAddress((void**)&cw,   g_cw);
    cudaGetSymbolAddress((void**)&wt,   g_wt);
    cudaGetSymbolAddress((void**)&pp,   g_pp);
    cudaGetSymbolAddress((void**)&pm,   g_pm);
    cudaGetSymbolAddress((void**)&pool, g_pool);

    // CSR build + weight transpose (once per launch)
    zero4_kernel<<<(MM / 4 + 255) / 256, 256>>>((float4*)cnti, MM / 4);
    count_kernel<<<(ETOT + 255) / 256, 256>>>(ei, emask, cnti);
    psum_kernel<<<64, 1024>>>(cnti, bsum);
    emit_kernel<<<64, 1024>>>(cnti, bsum, off, cur);
    fill_kernel<<<(ETOT + 255) / 256, 256>>>(ei, emask, cur, csrc, cw);
    wtrans_kernel<<<7, 256>>>(sW, nW, inW, wt);

    // input projection (HMMA tf32)
    input_mma_kernel<<<MM / 128, 256>>>(feats, wt + (size_t)6 * HH * HH, inb, x0);

    float* xin = x0;
    float* xo  = x1;
    for (int l = 0; l < 3; l++) {
        agg_csr_kernel<<<MM * 32 / 256, 256>>>(xin, off, csrc, cw, agg);
        layer_mma_kernel<<<MM / 128, 256>>>(xin, agg,
                                            wt + (size_t)(l * 2) * HH * HH,
                                            wt + (size_t)(l * 2 + 1) * HH * HH,
                                            sb + l * HH, nb + l * HH,
                                            lng + l * HH, lnb + l * HH,
                                            nmask, xo);
        float* t = xin; xin = xo; xo = t;
    }

    pool_partial_kernel<<<256, 256>>>(xin, nmask, pp, pm);
    pool_final_kernel<<<BB, 128>>>(pp, pm, nmask, pool);
    mlp_kernel<<<BB, 256>>>(pool, w1, b1, w2, b2, (float*)d_out);
}

// round 7
// speedup vs baseline: 5.3501x; 1.2974x over previous
#include <cuda_runtime.h>
#include <cuda_fp16.h>
#include <math.h>
#include <stdint.h>

#define BB 8
#define NN 8192
#define EE 65536
#define FIN 64
#define HH 128
#define OUTD 256
#define MM (BB*NN)
#define ETOT (BB*EE)

// ---------------- scratch ----------------
__device__ __half g_xh0[MM*HH];        // 16 MB activations ping
__device__ __half g_xh1[MM*HH];        // 16 MB activations pong
__device__ __half g_aggh[MM*HH];       // 16 MB aggregated means
__device__ int    g_cnti[MM];
__device__ int    g_off[MM + 4];
__device__ int    g_cur[MM];
__device__ int    g_bsum[64];
__device__ int    g_csrc[ETOT];
__device__ float  g_cw[ETOT];
__device__ uint32_t g_wth[6*HH*HH/2 + HH*FIN/2];  // fp16x2-packed W^T
__device__ float  g_pp[256*128];
__device__ float  g_pm[256*128];
__device__ float  g_pool[BB*2*HH];

// ---------------- fp16 helpers ----------------
__device__ __forceinline__ uint32_t pkh2(float x, float y) {
    __half2 h = __floats2half2_rn(x, y);
    return *reinterpret_cast<uint32_t*>(&h);
}
__device__ __forceinline__ float2 uph2(uint32_t v) {
    return __half22float2(*reinterpret_cast<const __half2*>(&v));
}
__device__ __forceinline__ void mma_f16(float* c, const uint32_t* a, uint32_t b0, uint32_t b1) {
    asm volatile("mma.sync.aligned.m16n8k16.row.col.f32.f16.f16.f32 "
                 "{%0,%1,%2,%3}, {%4,%5,%6,%7}, {%8,%9}, {%0,%1,%2,%3};"
                 : "+f"(c[0]), "+f"(c[1]), "+f"(c[2]), "+f"(c[3])
                 : "r"(a[0]), "r"(a[1]), "r"(a[2]), "r"(a[3]), "r"(b0), "r"(b1));
}

// ---------------- zero helper ----------------
__global__ void zero4_kernel(float4* __restrict__ p, int n4) {
    int i = blockIdx.x * blockDim.x + threadIdx.x;
    if (i < n4) p[i] = make_float4(0.f, 0.f, 0.f, 0.f);
}

// ---------------- CSR build ----------------
__global__ void count_kernel(const int* __restrict__ ei, const float* __restrict__ emask,
                             int* __restrict__ cnti) {
    int e = blockIdx.x * blockDim.x + threadIdx.x;
    if (e >= ETOT) return;
    int b = e / EE, ee = e - b * EE;
    if (emask[e] != 0.f) {
        int tgt = ei[b * 2 * EE + EE + ee] + b * NN;
        atomicAdd(&cnti[tgt], 1);
    }
}

__global__ void psum_kernel(const int* __restrict__ cnt, int* __restrict__ bsum) {
    __shared__ int sh[1024];
    int t = threadIdx.x;
    sh[t] = cnt[blockIdx.x * 1024 + t];
    __syncthreads();
    for (int d = 512; d; d >>= 1) {
        if (t < d) sh[t] += sh[t + d];
        __syncthreads();
    }
    if (t == 0) bsum[blockIdx.x] = sh[0];
}

__global__ void emit_kernel(const int* __restrict__ cnt, const int* __restrict__ bsum,
                            int* __restrict__ off, int* __restrict__ cur) {
    __shared__ int sh[1024];
    __shared__ int bpre, btot;
    int t = threadIdx.x, g = blockIdx.x * 1024 + t;
    int v = cnt[g];
    sh[t] = v;
    if (t == 0) {
        int p = 0, tot = 0;
        for (int i = 0; i < 64; i++) {
            int s = bsum[i];
            if (i < blockIdx.x) p += s;
            tot += s;
        }
        bpre = p;
        btot = tot;
    }
    __syncthreads();
    for (int d = 1; d < 1024; d <<= 1) {
        int u = (t >= d) ? sh[t - d] : 0;
        __syncthreads();
        sh[t] += u;
        __syncthreads();
    }
    int ex = sh[t] - v + bpre;
    off[g] = ex;
    cur[g] = ex;
    if (blockIdx.x == 63 && t == 1023) off[MM] = btot;
}

__global__ void fill_kernel(const int* __restrict__ ei, const float* __restrict__ emask,
                            int* __restrict__ cur, int* __restrict__ csrc,
                            float* __restrict__ cw) {
    int e = blockIdx.x * blockDim.x + threadIdx.x;
    if (e >= ETOT) return;
    int b = e / EE, ee = e - b * EE;
    float m = emask[e];
    if (m == 0.f) return;
    int src = ei[b * 2 * EE + ee] + b * NN;
    int tgt = ei[b * 2 * EE + EE + ee] + b * NN;
    int slot = atomicAdd(&cur[tgt], 1);
    csrc[slot] = src;
    cw[slot] = m;
}

// ---------------- weight transpose + fp16 pack ----------------
// mats 0..5: wth[n][k/2] packed from W[k][n] (128x128). mat 6: inW^T (128x64 k).
#define WT6 (6*HH*HH/2)
__global__ void wtrans_kernel(const float* __restrict__ sW, const float* __restrict__ nW,
                              const float* __restrict__ inW, uint32_t* __restrict__ wth) {
    int mat = blockIdx.x;
    if (mat < 6) {
        int l = mat >> 1, pass = mat & 1;
        const float* src = (pass ? nW : sW) + (size_t)l * HH * HH;
        uint32_t* dst = wth + (size_t)mat * (HH * HH / 2);
        for (int idx = threadIdx.x; idx < HH * HH / 2; idx += blockDim.x) {
            int n = idx >> 6, kk = idx & 63;
            dst[n * 64 + kk] = pkh2(src[(2 * kk) * HH + n], src[(2 * kk + 1) * HH + n]);
        }
    } else {
        uint32_t* dst = wth + WT6;
        for (int idx = threadIdx.x; idx < HH * FIN / 2; idx += blockDim.x) {
            int n = idx >> 5, kk = idx & 31;
            dst[n * 32 + kk] = pkh2(inW[(2 * kk) * HH + n], inW[(2 * kk + 1) * HH + n]);
        }
    }
}

// ---------------- CSR aggregation: warp per node, fp16 gather ----------------
__global__ void agg_csr_kernel(const __half* __restrict__ xh, const int* __restrict__ off,
                               const int* __restrict__ csrc, const float* __restrict__ cw,
                               __half* __restrict__ outh) {
    int warp = (blockIdx.x * blockDim.x + threadIdx.x) >> 5;
    int lane = threadIdx.x & 31;
    if (warp >= MM) return;
    const uint2* xv = (const uint2*)xh;   // 4 halves per uint2; 32 uint2 per row
    int beg = off[warp], end = off[warp + 1];
    float ax = 0.f, ay = 0.f, az = 0.f, aw = 0.f, ws = 0.f;
    int e = beg;
    for (; e + 2 <= end; e += 2) {
        int s0 = csrc[e], s1 = csrc[e + 1];
        float w0 = cw[e], w1 = cw[e + 1];
        uint2 u0 = xv[(size_t)s0 * 32 + lane];
        uint2 u1 = xv[(size_t)s1 * 32 + lane];
        float2 p0 = uph2(u0.x), q0 = uph2(u0.y);
        float2 p1 = uph2(u1.x), q1 = uph2(u1.y);
        ax += p0.x * w0 + p1.x * w1;
        ay += p0.y * w0 + p1.y * w1;
        az += q0.x * w0 + q1.x * w1;
        aw += q0.y * w0 + q1.y * w1;
        ws += w0 + w1;
    }
    if (e < end) {
        int s0 = csrc[e];
        float w0 = cw[e];
        uint2 u0 = xv[(size_t)s0 * 32 + lane];
        float2 p0 = uph2(u0.x), q0 = uph2(u0.y);
        ax += p0.x * w0; ay += p0.y * w0; az += q0.x * w0; aw += q0.y * w0;
        ws += w0;
    }
    float inv = 1.0f / fmaxf(ws, 1.0f);
    uint2 o;
    o.x = pkh2(ax * inv, ay * inv);
    o.y = pkh2(az * inv, aw * inv);
    ((uint2*)outh)[(size_t)warp * 32 + lane] = o;
}

// ================= fp16 HMMA GEMMs: CTA 128x128, warps 4(M) x 2(N) =================
// smem tile: 128 rows x 16 uint32 (32 halves), stride 20 (conflict-free frags)
#define PSTR 20

// ---------------- input GEMM: xh0 = relu(feats @ inW + inb) ----------------
__global__ void __launch_bounds__(256, 2)
input_mma_kernel(const float* __restrict__ A, const uint32_t* __restrict__ Wh,
                 const float* __restrict__ bias, __half* __restrict__ xout) {
    __shared__ __align__(16) uint32_t As[128 * PSTR];
    __shared__ __align__(16) uint32_t Bs[128 * PSTR];

    const int tid = threadIdx.x;
    const int wid = tid >> 5, lane = tid & 31;
    const int wm = wid & 3, wn = wid >> 2;
    const int g = lane >> 2, t = lane & 3;
    const int m0 = blockIdx.x * 128;

    float acc[2][8][4];
#pragma unroll
    for (int mi = 0; mi < 2; mi++)
#pragma unroll
        for (int ni = 0; ni < 8; ni++)
#pragma unroll
            for (int c = 0; c < 4; c++) acc[mi][ni][c] = 0.f;

    const float* Asrc = A + (size_t)m0 * FIN;

#pragma unroll 1
    for (int ch = 0; ch < 2; ch++) {
        __syncthreads();
        // A: 128 rows x 32 fp32 -> fp16; 1024 float4, 4/thread
#pragma unroll
        for (int u = 0; u < 4; u++) {
            int idx = u * 256 + tid;
            int row = idx >> 3, c4 = idx & 7;
            float4 v = *(const float4*)&Asrc[(size_t)row * FIN + ch * 32 + c4 * 4];
            uint2 o = make_uint2(pkh2(v.x, v.y), pkh2(v.z, v.w));
            *(uint2*)&As[row * PSTR + c4 * 2] = o;
        }
        // B: 128 n x 16 uint32 fp16 direct; 512 uint4, 2/thread
#pragma unroll
        for (int u = 0; u < 2; u++) {
            int idx = u * 256 + tid;
            int row = idx >> 2, q = idx & 3;
            uint4 w = *(const uint4*)&Wh[(size_t)row * 32 + ch * 16 + q * 4];
            *(uint4*)&Bs[row * PSTR + q * 4] = w;
        }
        __syncthreads();
#pragma unroll
        for (int ks = 0; ks < 2; ks++) {
            uint32_t a[2][4], b[8][2];
#pragma unroll
            for (int mi = 0; mi < 2; mi++) {
                int base = (wm * 32 + mi * 16 + g) * PSTR + ks * 8 + t;
                a[mi][0] = As[base];
                a[mi][1] = As[base + 8 * PSTR];
                a[mi][2] = As[base + 4];
                a[mi][3] = As[base + 8 * PSTR + 4];
            }
#pragma unroll
            for (int ni = 0; ni < 8; ni++) {
                int nb = (wn * 64 + ni * 8 + g) * PSTR + ks * 8 + t;
                b[ni][0] = Bs[nb];
                b[ni][1] = Bs[nb + 4];
            }
#pragma unroll
            for (int mi = 0; mi < 2; mi++)
#pragma unroll
                for (int ni = 0; ni < 8; ni++)
                    mma_f16(acc[mi][ni], a[mi], b[ni][0], b[ni][1]);
        }
    }

    // epilogue: bias + relu -> fp16
    float cb[16];
#pragma unroll
    for (int ni = 0; ni < 8; ni++)
#pragma unroll
        for (int j = 0; j < 2; j++)
            cb[ni * 2 + j] = bias[wn * 64 + ni * 8 + 2 * t + j];
    uint32_t* xo32 = (uint32_t*)xout;
#pragma unroll
    for (int mi = 0; mi < 2; mi++)
#pragma unroll
        for (int h = 0; h < 2; h++) {
            int grow = m0 + wm * 32 + mi * 16 + g + 8 * h;
#pragma unroll
            for (int ni = 0; ni < 8; ni++) {
                float ox = fmaxf(acc[mi][ni][2 * h]     + cb[ni * 2],     0.f);
                float oy = fmaxf(acc[mi][ni][2 * h + 1] + cb[ni * 2 + 1], 0.f);
                xo32[(size_t)grow * 64 + wn * 32 + ni * 4 + t] = pkh2(ox, oy);
            }
        }
}

// ---------------- fused layer: xh_out = LN(relu(x@Ws + agg@Wn + b)) * mask ----------------
__global__ void __launch_bounds__(256, 2)
layer_mma_kernel(const __half* __restrict__ xh, const __half* __restrict__ aggh,
                 const uint32_t* __restrict__ Wsh, const uint32_t* __restrict__ Wnh,
                 const float* __restrict__ bsb, const float* __restrict__ bnb,
                 const float* __restrict__ lng, const float* __restrict__ lnb,
                 const float* __restrict__ nmask, __half* __restrict__ xout) {
    __shared__ __align__(16) uint32_t As[128 * PSTR];
    __shared__ __align__(16) uint32_t Bs[128 * PSTR];
    __shared__ float red[128][4];

    const int tid = threadIdx.x;
    const int wid = tid >> 5, lane = tid & 31;
    const int wm = wid & 3, wn = wid >> 2;
    const int g = lane >> 2, t = lane & 3;
    const int m0 = blockIdx.x * 128;

    float acc[2][8][4];
#pragma unroll
    for (int mi = 0; mi < 2; mi++)
#pragma unroll
        for (int ni = 0; ni < 8; ni++)
#pragma unroll
            for (int c = 0; c < 4; c++) acc[mi][ni][c] = 0.f;

    const uint32_t* Apass[2] = {(const uint32_t*)xh + (size_t)m0 * 64,
                                (const uint32_t*)aggh + (size_t)m0 * 64};
    const uint32_t* Bpass[2] = {Wsh, Wnh};

    uint4 pva[2], pvb[2];
    // prefetch chunk 0
#pragma unroll
    for (int u = 0; u < 2; u++) {
        int idx = u * 256 + tid;
        int row = idx >> 2, q = idx & 3;
        pva[u] = *(const uint4*)&Apass[0][(size_t)row * 64 + q * 4];
        pvb[u] = *(const uint4*)&Bpass[0][(size_t)row * 64 + q * 4];
    }
#pragma unroll 1
    for (int ch = 0; ch < 8; ch++) {
        __syncthreads();
#pragma unroll
        for (int u = 0; u < 2; u++) {
            int idx = u * 256 + tid;
            int row = idx >> 2, q = idx & 3;
            *(uint4*)&As[row * PSTR + q * 4] = pva[u];
            *(uint4*)&Bs[row * PSTR + q * 4] = pvb[u];
        }
        __syncthreads();
        if (ch < 7) {
            int nc = ch + 1;
            const uint32_t* A_ = Apass[nc >> 2];
            const uint32_t* B_ = Bpass[nc >> 2];
            int koff = (nc & 3) * 16;
#pragma unroll
            for (int u = 0; u < 2; u++) {
                int idx = u * 256 + tid;
                int row = idx >> 2, q = idx & 3;
                pva[u] = *(const uint4*)&A_[(size_t)row * 64 + koff + q * 4];
                pvb[u] = *(const uint4*)&B_[(size_t)row * 64 + koff + q * 4];
            }
        }
#pragma unroll
        for (int ks = 0; ks < 2; ks++) {
            uint32_t a[2][4], b[8][2];
#pragma unroll
            for (int mi = 0; mi < 2; mi++) {
                int base = (wm * 32 + mi * 16 + g) * PSTR + ks * 8 + t;
                a[mi][0] = As[base];
                a[mi][1] = As[base + 8 * PSTR];
                a[mi][2] = As[base + 4];
                a[mi][3] = As[base + 8 * PSTR + 4];
            }
#pragma unroll
            for (int ni = 0; ni < 8; ni++) {
                int nb = (wn * 64 + ni * 8 + g) * PSTR + ks * 8 + t;
                b[ni][0] = Bs[nb];
                b[ni][1] = Bs[nb + 4];
            }
#pragma unroll
            for (int mi = 0; mi < 2; mi++)
#pragma unroll
                for (int ni = 0; ni < 8; ni++)
                    mma_f16(acc[mi][ni], a[mi], b[ni][0], b[ni][1]);
        }
    }

    // ---- epilogue: bias + relu + layernorm + mask -> fp16 ----
    float cb[16], cgv[16], cbv[16];
#pragma unroll
    for (int ni = 0; ni < 8; ni++)
#pragma unroll
        for (int j = 0; j < 2; j++) {
            int c = wn * 64 + ni * 8 + 2 * t + j;
            cb[ni * 2 + j]  = bsb[c] + bnb[c];
            cgv[ni * 2 + j] = lng[c];
            cbv[ni * 2 + j] = lnb[c];
        }
#pragma unroll
    for (int mi = 0; mi < 2; mi++)
#pragma unroll
        for (int h = 0; h < 2; h++) {
            float s1 = 0.f, s2 = 0.f;
#pragma unroll
            for (int ni = 0; ni < 8; ni++)
#pragma unroll
                for (int j = 0; j < 2; j++) {
                    float v = fmaxf(acc[mi][ni][2 * h + j] + cb[ni * 2 + j], 0.f);
                    acc[mi][ni][2 * h + j] = v;
                    s1 += v;
                    s2 += v * v;
                }
            s1 += __shfl_xor_sync(0xffffffffu, s1, 1);
            s1 += __shfl_xor_sync(0xffffffffu, s1, 2);
            s2 += __shfl_xor_sync(0xffffffffu, s2, 1);
            s2 += __shfl_xor_sync(0xffffffffu, s2, 2);
            if (t == 0) {
                int row = wm * 32 + mi * 16 + g + 8 * h;
                red[row][wn * 2]     = s1;
                red[row][wn * 2 + 1] = s2;
            }
        }
    __syncthreads();
    uint32_t* xo32 = (uint32_t*)xout;
#pragma unroll
    for (int mi = 0; mi < 2; mi++)
#pragma unroll
        for (int h = 0; h < 2; h++) {
            int row = wm * 32 + mi * 16 + g + 8 * h;
            float s1 = red[row][0] + red[row][2];
            float s2 = red[row][1] + red[row][3];
            float mean = s1 * (1.0f / 128.0f);
            float var = fmaxf(s2 * (1.0f / 128.0f) - mean * mean, 0.f);
            float inv = rsqrtf(var + 1e-5f);
            int grow = m0 + row;
            float mk = nmask[grow];
#pragma unroll
            for (int ni = 0; ni < 8; ni++) {
                float ox = ((acc[mi][ni][2 * h]     - mean) * inv * cgv[ni * 2]     + cbv[ni * 2])     * mk;
                float oy = ((acc[mi][ni][2 * h + 1] - mean) * inv * cgv[ni * 2 + 1] + cbv[ni * 2 + 1]) * mk;
                xo32[(size_t)grow * 64 + wn * 32 + ni * 4 + t] = pkh2(ox, oy);
            }
        }
}

// ---------------- pool: two-stage (fp16 input) ----------------
__global__ void pool_partial_kernel(const __half* __restrict__ x, const float* __restrict__ nmask,
                                    float* __restrict__ pp, float* __restrict__ pm) {
    int blk = blockIdx.x;
    int b = blk >> 5, nc = blk & 31;
    int t = threadIdx.x;
    int c = t & 127, half = t >> 7;
    float s = 0.f, mx = -INFINITY;
    for (int i = 0; i < 128; i++) {
        int n = nc * 256 + i * 2 + half;
        float mk = nmask[b * NN + n];
        float v = __half2float(x[((size_t)(b * NN + n)) * HH + c]) * mk;
        s += v;
        if (mk > 0.f) mx = fmaxf(mx, v);
    }
    __shared__ float sh[256];
    sh[t] = s;
    __syncthreads();
    if (half == 0) pp[blk * 128 + c] = sh[c] + sh[c + 128];
    __syncthreads();
    sh[t] = mx;
    __syncthreads();
    if (half == 0) pm[blk * 128 + c] = fmaxf(sh[c], sh[c + 128]);
}

__global__ void pool_final_kernel(const float* __restrict__ pp, const float* __restrict__ pm,
                                  const float* __restrict__ nmask, float* __restrict__ pool) {
    int b = blockIdx.x, c = threadIdx.x;
    float s = 0.f, mx = -INFINITY;
#pragma unroll
    for (int k = 0; k < 32; k++) {
        s += pp[(b * 32 + k) * 128 + c];
        mx = fmaxf(mx, pm[(b * 32 + k) * 128 + c]);
    }
    float cv = 0.f;
    for (int n = c; n < NN; n += 128) cv += nmask[b * NN + n];
    __shared__ float sc[128];
    sc[c] = cv;
    __syncthreads();
    for (int d = 64; d; d >>= 1) {
        if (c < d) sc[c] += sc[c + d];
        __syncthreads();
    }
    float cnt = fmaxf(sc[0], 1.f);
    pool[b * 256 + c] = s / cnt;
    pool[b * 256 + 128 + c] = mx;
}

// ---------------- output MLP ----------------
__global__ void mlp_kernel(const float* __restrict__ pool, const float* __restrict__ W1,
                           const float* __restrict__ b1, const float* __restrict__ W2,
                           const float* __restrict__ b2, float* __restrict__ out) {
    __shared__ float gs[256], hs[128];
    int b = blockIdx.x, tid = threadIdx.x;
    gs[tid] = pool[b * 256 + tid];
    __syncthreads();
    if (tid < 128) {
        float a = b1[tid];
        for (int k = 0; k < 256; k++) a = fmaf(gs[k], W1[k * 128 + tid], a);
        hs[tid] = fmaxf(a, 0.f);
    }
    __syncthreads();
    float a = b2[tid];
    for (int k = 0; k < 128; k++) a = fmaf(hs[k], W2[k * 256 + tid], a);
    out[b * 256 + tid] = a;
}

// ---------------- launch ----------------
extern "C" void kernel_launch(void* const* d_in, const int* in_sizes, int n_in,
                              void* d_out, int out_size) {
    const float* feats = (const float*)d_in[0];
    const int*   ei    = (const int*)d_in[1];
    const float* nmask = (const float*)d_in[2];
    const float* emask = (const float*)d_in[3];
    const float* inW   = (const float*)d_in[4];
    const float* inb   = (const float*)d_in[5];
    const float* sW    = (const float*)d_in[6];
    const float* sb    = (const float*)d_in[7];
    const float* nW    = (const float*)d_in[8];
    const float* nb    = (const float*)d_in[9];
    const float* lng   = (const float*)d_in[10];
    const float* lnb   = (const float*)d_in[11];
    const float* w1    = (const float*)d_in[12];
    const float* b1    = (const float*)d_in[13];
    const float* w2    = (const float*)d_in[14];
    const float* b2    = (const float*)d_in[15];

    __half *xh0, *xh1, *aggh;
    float *pool, *cw, *pp, *pm;
    uint32_t* wth;
    int *cnti, *off, *cur, *csrc, *bsum;
    cudaGetSymbolAddress((void**)&xh0,  g_xh0);
    cudaGetSymbolAddress((void**)&xh1,  g_xh1);
    cudaGetSymbolAddress((void**)&aggh, g_aggh);
    cudaGetSymbolAddress((void**)&cnti, g_cnti);
    cudaGetSymbolAddress((void**)&off,  g_off);
    cudaGetSymbolAddress((void**)&cur,  g_cur);
    cudaGetSymbolAddress((void**)&bsum, g_bsum);
    cudaGetSymbolAddress((void**)&csrc, g_csrc);
    cudaGetSymbolAddress((void**)&cw,   g_cw);
    cudaGetSymbolAddress((void**)&wth,  g_wth);
    cudaGetSymbolAddress((void**)&pp,   g_pp);
    cudaGetSymbolAddress((void**)&pm,   g_pm);
    cudaGetSymbolAddress((void**)&pool, g_pool);

    // CSR build + weight pack (once per launch)
    zero4_kernel<<<(MM / 4 + 255) / 256, 256>>>((float4*)cnti, MM / 4);
    count_kernel<<<(ETOT + 255) / 256, 256>>>(ei, emask, cnti);
    psum_kernel<<<64, 1024>>>(cnti, bsum);
    emit_kernel<<<64, 1024>>>(cnti, bsum, off, cur);
    fill_kernel<<<(ETOT + 255) / 256, 256>>>(ei, emask, cur, csrc, cw);
    wtrans_kernel<<<7, 256>>>(sW, nW, inW, wth);

    // input projection (fp16 HMMA)
    input_mma_kernel<<<MM / 128, 256>>>(feats, wth + WT6, inb, xh0);

    __half* xin = xh0;
    __half* xo  = xh1;
    for (int l = 0; l < 3; l++) {
        agg_csr_kernel<<<MM * 32 / 256, 256>>>(xin, off, csrc, cw, aggh);
        layer_mma_kernel<<<MM / 128, 256>>>(xin, aggh,
                                            wth + (size_t)(l * 2) * (HH * HH / 2),
                                            wth + (size_t)(l * 2 + 1) * (HH * HH / 2),
                                            sb + l * HH, nb + l * HH,
                                            lng + l * HH, lnb + l * HH,
                                            nmask, xo);
        __half* t = xin; xin = xo; xo = t;
    }

    pool_partial_kernel<<<256, 256>>>(xin, nmask, pp, pm);
    pool_final_kernel<<<BB, 128>>>(pp, pm, nmask, pool);
    mlp_kernel<<<BB, 256>>>(pool, w1, b1, w2, b2, (float*)d_out);
}